// round 8
// baseline (speedup 1.0000x reference)
#include <cuda_runtime.h>
#include <cuda_fp16.h>
#include <math.h>
#include <stdint.h>

#define B_ROWS   8192
#define D_INF    2048
#define D_BOT    1024
#define C_CLS    1000
#define C_PAD    1024
#define SHARE    500
#define NEG_FILL (-1e9f)
#define EPSN     1e-12f
#define SW       512.0f           // weight pre-scale (keeps fp16 m-components normal)
#define SA4      32.0f            // GEMM4 A pre-scale

// ===================== scratch (static device globals) =====================
__device__ __align__(1024) __half g_feat2 [2][(size_t)B_ROWS * D_INF];
__device__ __align__(1024) __half g_Wb2   [2][(size_t)D_BOT  * D_INF];
__device__ __align__(1024) __half g_feats2[2][(size_t)B_ROWS * D_BOT];
__device__ __align__(1024) __half g_W1s   [2][(size_t)C_PAD  * D_BOT];
__device__ __align__(1024) __half g_sm1s  [2][(size_t)B_ROWS * C_PAD];
__device__ __align__(1024) __half g_cTs   [2][(size_t)D_BOT  * C_PAD];
__device__ __align__(1024) __half g_faug2 [2][(size_t)B_ROWS * D_BOT];
__device__ __align__(1024) __half g_W2s   [2][(size_t)C_PAD  * D_BOT];

// ===================== helpers =====================
__device__ __forceinline__ uint32_t smem_u32(const void* p) {
    return (uint32_t)__cvta_generic_to_shared(p);
}
__device__ __forceinline__ void cp16(uint32_t sdst, const void* gsrc) {
    asm volatile("cp.async.cg.shared.global [%0], [%1], 16;" :: "r"(sdst), "l"(gsrc));
}
#define CP_COMMIT() asm volatile("cp.async.commit_group;" ::: "memory")
#define CP_WAIT1()  asm volatile("cp.async.wait_group 1;" ::: "memory")

#define LDSM_X4(r0, r1, r2, r3, addr) \
    asm volatile("ldmatrix.sync.aligned.m8n8.x4.shared.b16 {%0,%1,%2,%3}, [%4];" \
        : "=r"(r0), "=r"(r1), "=r"(r2), "=r"(r3) : "r"(addr))
#define LDSM_X2(r0, r1, addr) \
    asm volatile("ldmatrix.sync.aligned.m8n8.x2.shared.b16 {%0,%1}, [%2];" \
        : "=r"(r0), "=r"(r1) : "r"(addr))

__device__ __forceinline__ void mma_16816(float* c, const uint32_t* a, const uint32_t* b) {
    asm volatile(
        "mma.sync.aligned.m16n8k16.row.col.f32.f16.f16.f32 "
        "{%0,%1,%2,%3}, {%4,%5,%6,%7}, {%8,%9}, {%0,%1,%2,%3};"
        : "+f"(c[0]), "+f"(c[1]), "+f"(c[2]), "+f"(c[3])
        : "r"(a[0]), "r"(a[1]), "r"(a[2]), "r"(a[3]), "r"(b[0]), "r"(b[1]));
}

__device__ __forceinline__ void split2h(float x, __half& h, __half& m) {
    h = __float2half_rn(x);
    m = __float2half_rn(x - __half2float(h));
}

// swizzled smem byte offset within a tile: row (0..127), 16B-chunk c (0..3)
__device__ __forceinline__ uint32_t sw_off(int row, int c) {
    return (uint32_t)(row * 64 + ((c ^ ((row >> 1) & 3)) << 4));
}

// ===================== fp16 split GEMM via mma.sync =====================
// C[8192, Nout](+epilogue) = escale * sum_terms A_c[8192,K] @ B_c[1024,K]^T
// NC = 2 components per operand. NTERMS = 4 (all pairs) or 3 (drop m*m).
// block tile 128x128, BK=32, 8 warps (warp 64x32), 3-stage swizzled ring, 2 CTA/SM.
//  MODE 0: v = escale*acc + bias[n]; store stride D_BOT; also split2 -> oc0/oc1
//  MODE 1: v = escale*acc;           store stride Nout, guard n<Nout
//  MODE 2: v = escale*acc + aux[m*D_BOT+n]; store stride D_BOT
//  MODE 3: v = escale*acc;           store stride Nout, guard
template <int NTERMS, int MODE>
__global__ void __launch_bounds__(256, 2)
gemm_mma(const __half* __restrict__ A, size_t sA,
         const __half* __restrict__ B, size_t sB,
         float* __restrict__ C, int K, int Nout, float escale,
         const float* __restrict__ aux,
         __half* __restrict__ oc0, __half* __restrict__ oc1)
{
    extern __shared__ __align__(128) char smem[];
    const uint32_t sb = smem_u32(smem);
    const int tid = threadIdx.x;
    const int wid = tid >> 5;
    const int lane = tid & 31;
    const int bm = blockIdx.y * 128;
    const int bn = blockIdx.x * 128;

    constexpr int TILEB = 128 * 64;            // 8192 B (64B rows, XOR-swizzled chunks)
    constexpr int STAGE = 4 * TILEB;           // 32768 B: 2 A-tiles + 2 B-tiles

    const int wm = (wid >> 2) * 64;
    const int wn = (wid & 3) * 32;

    // per-lane ldsm row indices (within warp tile) and their swizzle keys
    const int a_r = lane & 15;                 // A: rows wm+mt*16+a_r
    const int b_r = lane & 7;                  // B: rows wn+nt*8+b_r
    const int a_c0 = lane >> 4;                // A chunk base (0/1)
    const int b_c0 = (lane >> 3) & 1;          // B chunk base (0/1)

    const int l_row = tid >> 1;                // loader row 0..127
    const int l_half = tid & 1;                // chunks {2h, 2h+1}

    float acc[4][4][4];
#pragma unroll
    for (int i = 0; i < 4; i++)
#pragma unroll
        for (int j = 0; j < 4; j++)
#pragma unroll
            for (int q = 0; q < 4; q++) acc[i][j][q] = 0.f;

    const int nch = K >> 5;

    auto load_chunk = [&](int ci) {
        const int s = ci % 3;
        const int k0 = ci << 5;
        const uint32_t st = sb + (uint32_t)s * STAGE;
#pragma unroll
        for (int c = 0; c < 4; c++) {
            const __half* base = (c < 2)
                ? A + (size_t)c * sA + (size_t)bm * K + k0
                : B + (size_t)(c - 2) * sB + (size_t)bn * K + k0;
#pragma unroll
            for (int j = 0; j < 2; j++) {
                const int ch = l_half * 2 + j;
                cp16(st + (uint32_t)(c * TILEB) + sw_off(l_row, ch),
                     base + (size_t)l_row * K + ch * 8);
            }
        }
        CP_COMMIT();
    };

    load_chunk(0);
    load_chunk(1);

    for (int i = 0; i < nch; i++) {
        CP_WAIT1();
        __syncthreads();
        if (i + 2 < nch) load_chunk(i + 2);   // targets stage (i-1)%3, freed by this sync
        const uint32_t st = sb + (uint32_t)(i % 3) * STAGE;
#pragma unroll
        for (int kk = 0; kk < 2; kk++) {
            uint32_t bfr[2][4][2];
#pragma unroll
            for (int c = 0; c < 2; c++)
#pragma unroll
                for (int nt = 0; nt < 4; nt++) {
                    const int row = wn + nt * 8 + b_r;
                    LDSM_X2(bfr[c][nt][0], bfr[c][nt][1],
                            st + (uint32_t)((2 + c) * TILEB) + sw_off(row, kk * 2 + b_c0));
                }
#pragma unroll
            for (int ca = 0; ca < 2; ca++) {
                uint32_t afr[4][4];
#pragma unroll
                for (int mt = 0; mt < 4; mt++) {
                    const int row = wm + mt * 16 + a_r;
                    LDSM_X4(afr[mt][0], afr[mt][1], afr[mt][2], afr[mt][3],
                            st + (uint32_t)(ca * TILEB) + sw_off(row, kk * 2 + a_c0));
                }
#pragma unroll
                for (int cb = 0; cb < 2; cb++) {
                    if (NTERMS == 4 || ca + cb < 2) {
#pragma unroll
                        for (int mt = 0; mt < 4; mt++)
#pragma unroll
                            for (int nt = 0; nt < 4; nt++)
                                mma_16816(acc[mt][nt], afr[mt], bfr[cb][nt]);
                    }
                }
            }
        }
    }

    // ---------------- epilogue ----------------
    const int r0 = lane >> 2;
    const int c0 = (lane & 3) * 2;
#pragma unroll
    for (int mt = 0; mt < 4; mt++) {
#pragma unroll
        for (int half = 0; half < 2; half++) {
            const int m = bm + wm + mt * 16 + r0 + half * 8;
#pragma unroll
            for (int nt = 0; nt < 4; nt++) {
                const int n = bn + wn + nt * 8 + c0;
                float v0 = acc[mt][nt][half * 2 + 0] * escale;
                float v1 = acc[mt][nt][half * 2 + 1] * escale;
                if (MODE == 0) {
                    const float2 bs = *reinterpret_cast<const float2*>(aux + n);
                    v0 += bs.x; v1 += bs.y;
                    const size_t o = (size_t)m * D_BOT + n;
                    *reinterpret_cast<float2*>(C + o) = make_float2(v0, v1);
                    __half h0, mm0, h1, mm1;
                    split2h(v0, h0, mm0); split2h(v1, h1, mm1);
                    __half2 ph; ph.x = h0; ph.y = h1;
                    __half2 pm; pm.x = mm0; pm.y = mm1;
                    *reinterpret_cast<__half2*>(oc0 + o) = ph;
                    *reinterpret_cast<__half2*>(oc1 + o) = pm;
                } else if (MODE == 2) {
                    const float2 r = *reinterpret_cast<const float2*>(aux + (size_t)m * D_BOT + n);
                    v0 += r.x; v1 += r.y;
                    *reinterpret_cast<float2*>(C + (size_t)m * D_BOT + n) = make_float2(v0, v1);
                } else {
                    if (n < Nout)
                        *reinterpret_cast<float2*>(C + (size_t)m * Nout + n) = make_float2(v0, v1);
                }
            }
        }
    }
}

// ===================== split kernels =====================
__global__ void split2_scale(const float* __restrict__ src, int src_rows, int colshift,
                             float scale,
                             __half* __restrict__ c0, __half* __restrict__ c1, int pad_rows)
{
    const size_t total4 = ((size_t)pad_rows << colshift) >> 2;
    for (size_t i = blockIdx.x * (size_t)blockDim.x + threadIdx.x; i < total4;
         i += (size_t)gridDim.x * blockDim.x) {
        const int row = (int)((i * 4) >> colshift);
        float4 v = (row < src_rows) ? reinterpret_cast<const float4*>(src)[i]
                                    : make_float4(0.f, 0.f, 0.f, 0.f);
        v.x *= scale; v.y *= scale; v.z *= scale; v.w *= scale;
        const float x[4] = {v.x, v.y, v.z, v.w};
        __half2 ph[2], pm[2];
#pragma unroll
        for (int p = 0; p < 2; p++) {
            __half h0, m0, h1, m1;
            split2h(x[2 * p], h0, m0);
            split2h(x[2 * p + 1], h1, m1);
            ph[p].x = h0; ph[p].y = h1;
            pm[p].x = m0; pm[p].y = m1;
        }
        reinterpret_cast<__half2*>(c0)[i * 2 + 0] = ph[0];
        reinterpret_cast<__half2*>(c0)[i * 2 + 1] = ph[1];
        reinterpret_cast<__half2*>(c1)[i * 2 + 0] = pm[0];
        reinterpret_cast<__half2*>(c1)[i * 2 + 1] = pm[1];
    }
}

// fused: per-row L2 norm of features_aug, scaled split2 (x * SA4 / ||row||) -> faug2
__global__ void __launch_bounds__(256)
norm_split2(const float* __restrict__ src,
            __half* __restrict__ c0, __half* __restrict__ c1)
{
    const int row = blockIdx.x;
    const int t = threadIdx.x;
    float4 v = reinterpret_cast<const float4*>(src + (size_t)row * D_BOT)[t];
    float s = v.x * v.x + v.y * v.y + v.z * v.z + v.w * v.w;
    __shared__ float sh[256];
    sh[t] = s;
    __syncthreads();
#pragma unroll
    for (int k = 128; k > 0; k >>= 1) {
        if (t < k) sh[t] += sh[t + k];
        __syncthreads();
    }
    const float inv = SA4 / fmaxf(sqrtf(sh[0]), EPSN);
    v.x *= inv; v.y *= inv; v.z *= inv; v.w *= inv;
    const float x[4] = {v.x, v.y, v.z, v.w};
    const size_t base2 = ((size_t)row * D_BOT + t * 4) >> 1;
#pragma unroll
    for (int p = 0; p < 2; p++) {
        __half h0, m0, h1, m1;
        split2h(x[2 * p], h0, m0);
        split2h(x[2 * p + 1], h1, m1);
        __half2 ph; ph.x = h0; ph.y = h1;
        __half2 pm; pm.x = m0; pm.y = m1;
        reinterpret_cast<__half2*>(c0)[base2 + p] = ph;
        reinterpret_cast<__half2*>(c1)[base2 + p] = pm;
    }
}

// centroid [C,D_BOT] -> cT*SW split2, [D_BOT rows, C_PAD cols]
__global__ void transpose_split2(const float* __restrict__ src)
{
    __shared__ float tile[32][33];
    const int bx = blockIdx.x * 32;  // d
    const int by = blockIdx.y * 32;  // c
    const int x = bx + threadIdx.x;
#pragma unroll
    for (int i = 0; i < 32; i += 8) {
        const int c = by + threadIdx.y + i;
        tile[threadIdx.y + i][threadIdx.x] = (c < C_CLS) ? src[(size_t)c * D_BOT + x] * SW : 0.f;
    }
    __syncthreads();
    const int c2 = by + threadIdx.x;
#pragma unroll
    for (int i = 0; i < 32; i += 8) {
        const int d2 = bx + threadIdx.y + i;
        const float v = tile[threadIdx.x][threadIdx.y + i];
        __half h, m;
        split2h(v, h, m);
        const size_t o = (size_t)d2 * C_PAD + c2;
        g_cTs[0][o] = h;
        g_cTs[1][o] = m;
    }
}

// ===================== masked softmax -> sm1 split2 (col-padded, fp16) ==============
__global__ void __launch_bounds__(256)
mask_softmax(const float* __restrict__ logits)
{
    const int row = blockIdx.x;
    const float* x = logits + (size_t)row * C_CLS;
    const int t = threadIdx.x;

    float v[4];
    float lmax = -INFINITY;
    int limax = C_CLS;
#pragma unroll
    for (int i = 0; i < 4; i++) {
        const int j = t + i * 256;
        const float val = (j < C_CLS) ? x[j] : -INFINITY;
        v[i] = val;
        if (val > lmax) { lmax = val; limax = j; }
    }
    __shared__ float smax[256];
    __shared__ int   simax[256];
    smax[t] = lmax; simax[t] = limax;
    __syncthreads();
#pragma unroll
    for (int s = 128; s > 0; s >>= 1) {
        if (t < s) {
            const float o = smax[t + s]; const int oi = simax[t + s];
            if (o > smax[t] || (o == smax[t] && oi < simax[t])) { smax[t] = o; simax[t] = oi; }
        }
        __syncthreads();
    }
    const int predict = simax[0];
    const float rowmax = smax[0];
    const bool priv = (predict >= SHARE);

    float e[4];
    float lsum = 0.f;
#pragma unroll
    for (int i = 0; i < 4; i++) {
        const int j = t + i * 256;
        float ee = 0.f;
        if (j < C_CLS) {
            bool mask;
            if (j == predict) mask = false;
            else if (priv)    mask = true;
            else              mask = (j < SHARE);
            ee = expf((mask ? NEG_FILL : v[i]) - rowmax);
            lsum += ee;
        }
        e[i] = ee;
    }
    __shared__ float ssum[256];
    ssum[t] = lsum;
    __syncthreads();
#pragma unroll
    for (int s = 128; s > 0; s >>= 1) {
        if (t < s) ssum[t] += ssum[t + s];
        __syncthreads();
    }
    const float inv = 1.f / ssum[0];

    __half* o0 = g_sm1s[0] + (size_t)row * C_PAD;
    __half* o1 = g_sm1s[1] + (size_t)row * C_PAD;
#pragma unroll
    for (int i = 0; i < 4; i++) {
        const int j = t + i * 256;
        const float p = (j < C_CLS) ? e[i] * inv : 0.f;
        __half h, m;
        split2h(p, h, m);
        o0[j] = h;
        o1[j] = m;
    }
}

// ===================== plain row softmax =====================
__global__ void __launch_bounds__(256)
softmax_rows(const float* __restrict__ in, float* __restrict__ outp)
{
    const int row = blockIdx.x;
    const float* x = in + (size_t)row * C_CLS;
    const int t = threadIdx.x;
    float v[4];
    float lmax = -INFINITY;
#pragma unroll
    for (int i = 0; i < 4; i++) {
        const int j = t + i * 256;
        v[i] = (j < C_CLS) ? x[j] : -INFINITY;
        lmax = fmaxf(lmax, v[i]);
    }
    __shared__ float sh[256];
    sh[t] = lmax;
    __syncthreads();
#pragma unroll
    for (int s = 128; s > 0; s >>= 1) {
        if (t < s) sh[t] = fmaxf(sh[t], sh[t + s]);
        __syncthreads();
    }
    const float rowmax = sh[0];
    __syncthreads();
    float e[4];
    float lsum = 0.f;
#pragma unroll
    for (int i = 0; i < 4; i++) {
        const int j = t + i * 256;
        float ee = 0.f;
        if (j < C_CLS) { ee = expf(v[i] - rowmax); lsum += ee; }
        e[i] = ee;
    }
    sh[t] = lsum;
    __syncthreads();
#pragma unroll
    for (int s = 128; s > 0; s >>= 1) {
        if (t < s) sh[t] += sh[t + s];
        __syncthreads();
    }
    const float inv = 1.f / sh[0];
    float* o = outp + (size_t)row * C_CLS;
#pragma unroll
    for (int i = 0; i < 4; i++) {
        const int j = t + i * 256;
        if (j < C_CLS) o[j] = e[i] * inv;
    }
}

// =====================================================================
extern "C" void kernel_launch(void* const* d_in, const int* in_sizes, int n_in,
                              void* d_out, int out_size)
{
    const float* features = (const float*)d_in[0];
    const float* W_b      = (const float*)d_in[1];
    const float* b_b      = (const float*)d_in[2];
    const float* W1       = (const float*)d_in[3];
    const float* W2       = (const float*)d_in[4];
    const float* centroid = (const float*)d_in[5];

    float* out = (float*)d_out;
    float* feats        = out;
    float* features_aug = feats + (size_t)B_ROWS * D_BOT;
    float* outputs1     = features_aug + (size_t)B_ROWS * D_BOT;
    float* outputs2     = outputs1 + (size_t)B_ROWS * C_CLS;
    float* softmax_out  = outputs2 + (size_t)B_ROWS * C_CLS;

    __half *feat2, *Wb2, *feats2, *W1s, *sm1s, *cTs, *faug2, *W2s;
    cudaGetSymbolAddress((void**)&feat2,  g_feat2);
    cudaGetSymbolAddress((void**)&Wb2,    g_Wb2);
    cudaGetSymbolAddress((void**)&feats2, g_feats2);
    cudaGetSymbolAddress((void**)&W1s,    g_W1s);
    cudaGetSymbolAddress((void**)&sm1s,   g_sm1s);
    cudaGetSymbolAddress((void**)&cTs,    g_cTs);
    cudaGetSymbolAddress((void**)&faug2,  g_faug2);
    cudaGetSymbolAddress((void**)&W2s,    g_W2s);

    const size_t S_feat  = (size_t)B_ROWS * D_INF;
    const size_t S_Wb    = (size_t)D_BOT  * D_INF;
    const size_t S_feats = (size_t)B_ROWS * D_BOT;
    const size_t S_W1    = (size_t)C_PAD  * D_BOT;
    const size_t S_sm1   = (size_t)B_ROWS * C_PAD;
    const size_t S_cT    = (size_t)D_BOT  * C_PAD;

    constexpr int TILEB = 128 * 64;
    constexpr int SMEMG = 3 * 4 * TILEB;   // 98304 — still 2 CTAs/SM
    cudaFuncSetAttribute(gemm_mma<4, 0>, cudaFuncAttributeMaxDynamicSharedMemorySize, SMEMG);
    cudaFuncSetAttribute(gemm_mma<4, 1>, cudaFuncAttributeMaxDynamicSharedMemorySize, SMEMG);
    cudaFuncSetAttribute(gemm_mma<3, 2>, cudaFuncAttributeMaxDynamicSharedMemorySize, SMEMG);
    cudaFuncSetAttribute(gemm_mma<3, 3>, cudaFuncAttributeMaxDynamicSharedMemorySize, SMEMG);

    const dim3 blk(256);
    const dim3 grid8(8, 64);
    const float invSW = 1.0f / SW;

    // splits for GEMM1
    split2_scale<<<1024, blk>>>(features, B_ROWS, 11, 1.0f, feat2, feat2 + S_feat, B_ROWS);
    split2_scale<<<512,  blk>>>(W_b, D_BOT, 11, SW, Wb2, Wb2 + S_Wb, D_BOT);

    // GEMM1: feats = features @ W_b^T + b_b (epilogue emits feats2 split)
    gemm_mma<4, 0><<<grid8, blk, SMEMG>>>(feat2, S_feat, Wb2, S_Wb, feats, D_INF, D_BOT,
                                          invSW, b_b, feats2, feats2 + S_feats);

    // W1 split
    split2_scale<<<512, blk>>>(W1, C_CLS, 10, SW, W1s, W1s + S_W1, C_PAD);

    // GEMM2: outputs1 = feats @ W1^T
    gemm_mma<4, 1><<<grid8, blk, SMEMG>>>(feats2, S_feats, W1s, S_W1, outputs1, D_BOT, C_CLS,
                                          invSW, nullptr, nullptr, nullptr);

    // centroid^T split + masked softmax
    transpose_split2<<<dim3(D_BOT / 32, C_PAD / 32), dim3(32, 8)>>>(centroid);
    mask_softmax<<<B_ROWS, blk>>>(outputs1);

    // GEMM3: features_aug = sm1 @ centroid + feats
    gemm_mma<3, 2><<<grid8, blk, SMEMG>>>(sm1s, S_sm1, cTs, S_cT, features_aug, C_PAD, D_BOT,
                                          invSW, feats, nullptr, nullptr);

    // fused normalize (+*SA4) + split2
    norm_split2<<<B_ROWS, blk>>>(features_aug, faug2, faug2 + S_feats);
    split2_scale<<<512, blk>>>(W2, C_CLS, 10, SW, W2s, W2s + S_W1, C_PAD);

    // GEMM4: outputs2 = x @ W2^T / TEMP   (escale = 20 / (SW*SA4))
    gemm_mma<3, 3><<<grid8, blk, SMEMG>>>(faug2, S_feats, W2s, S_W1, outputs2, D_BOT, C_CLS,
                                          20.0f / (SW * SA4), nullptr, nullptr, nullptr);

    softmax_rows<<<B_ROWS, blk>>>(outputs2, softmax_out);
}

// round 9
// speedup vs baseline: 1.1267x; 1.1267x over previous
#include <cuda_runtime.h>
#include <cuda_fp16.h>
#include <math.h>
#include <stdint.h>

#define B_ROWS   8192
#define D_INF    2048
#define D_BOT    1024
#define C_CLS    1000
#define C_PAD    1024
#define SHARE    500
#define NEG_FILL (-1e9f)
#define EPSN     1e-12f
#define SW       512.0f           // weight pre-scale (keeps fp16 m-components normal)
#define SA4      32.0f            // GEMM4 A pre-scale

// ===================== scratch (static device globals) =====================
__device__ __align__(1024) __half g_feat2 [2][(size_t)B_ROWS * D_INF];
__device__ __align__(1024) __half g_Wb2   [2][(size_t)D_BOT  * D_INF];
__device__ __align__(1024) __half g_feats2[2][(size_t)B_ROWS * D_BOT];
__device__ __align__(1024) __half g_W1s   [2][(size_t)C_PAD  * D_BOT];
__device__ __align__(1024) __half g_sm1s  [2][(size_t)B_ROWS * C_PAD];
__device__ __align__(1024) __half g_cTs   [2][(size_t)D_BOT  * C_PAD];
__device__ __align__(1024) __half g_faug2 [2][(size_t)B_ROWS * D_BOT];
__device__ __align__(1024) __half g_W2s   [2][(size_t)C_PAD  * D_BOT];

// ===================== helpers =====================
__device__ __forceinline__ uint32_t smem_u32(const void* p) {
    return (uint32_t)__cvta_generic_to_shared(p);
}
__device__ __forceinline__ void cp16(uint32_t sdst, const void* gsrc) {
    asm volatile("cp.async.cg.shared.global [%0], [%1], 16;" :: "r"(sdst), "l"(gsrc));
}
#define CP_COMMIT() asm volatile("cp.async.commit_group;" ::: "memory")
#define CP_WAIT1()  asm volatile("cp.async.wait_group 1;" ::: "memory")

#define LDSM_X4(r0, r1, r2, r3, addr) \
    asm volatile("ldmatrix.sync.aligned.m8n8.x4.shared.b16 {%0,%1,%2,%3}, [%4];" \
        : "=r"(r0), "=r"(r1), "=r"(r2), "=r"(r3) : "r"(addr))
#define LDSM_X2(r0, r1, addr) \
    asm volatile("ldmatrix.sync.aligned.m8n8.x2.shared.b16 {%0,%1}, [%2];" \
        : "=r"(r0), "=r"(r1) : "r"(addr))

__device__ __forceinline__ void mma_16816(float* c, const uint32_t* a, const uint32_t* b) {
    asm volatile(
        "mma.sync.aligned.m16n8k16.row.col.f32.f16.f16.f32 "
        "{%0,%1,%2,%3}, {%4,%5,%6,%7}, {%8,%9}, {%0,%1,%2,%3};"
        : "+f"(c[0]), "+f"(c[1]), "+f"(c[2]), "+f"(c[3])
        : "r"(a[0]), "r"(a[1]), "r"(a[2]), "r"(a[3]), "r"(b[0]), "r"(b[1]));
}

__device__ __forceinline__ void split2h(float x, __half& h, __half& m) {
    h = __float2half_rn(x);
    m = __float2half_rn(x - __half2float(h));
}

// ===================== fp16 split GEMM via mma.sync =====================
// C[8192, Nout](+epilogue) = escale * sum_terms A_c[8192,K] @ B_c[1024,K]^T
// NC = 2 components per operand. NTERMS = 4 (all pairs) or 3 (drop m*m).
// block tile 128x128, BK=32, 8 warps (warp tile 64x32), 2-stage cp.async, 2 CTA/SM.
//  MODE 0: v = escale*acc + bias[n]; store stride D_BOT; also split2 -> oc0/oc1
//  MODE 1: v = escale*acc;           store stride Nout, guard n<Nout
//  MODE 2: v = escale*acc + aux[m*D_BOT+n]; store stride D_BOT
//  MODE 3: v = escale*acc;           store stride Nout, guard
template <int NTERMS, int MODE>
__global__ void __launch_bounds__(256, 2)
gemm_mma(const __half* __restrict__ A, size_t sA,
         const __half* __restrict__ B, size_t sB,
         float* __restrict__ C, int K, int Nout, float escale,
         const float* __restrict__ aux,
         __half* __restrict__ oc0, __half* __restrict__ oc1)
{
    extern __shared__ __align__(128) char smem[];
    const uint32_t sb = smem_u32(smem);
    const int tid = threadIdx.x;
    const int wid = tid >> 5;
    const int lane = tid & 31;
    const int bm = blockIdx.y * 128;
    const int bn = blockIdx.x * 128;

    constexpr int TILEB = 128 * 80;            // 10240 B (64B data + 16B pad per row)
    constexpr int STAGE = 4 * TILEB;           // 2 A-tiles + 2 B-tiles

    const int wm = (wid >> 2) * 64;
    const int wn = (wid & 3) * 32;

    const uint32_t a_lo = (uint32_t)((lane & 15) * 80 + (lane >> 4) * 16);
    const uint32_t b_lo = (uint32_t)((lane & 7) * 80 + ((lane >> 3) & 1) * 16);

    const int l_row0 = tid >> 2;
    const int l_seg = tid & 3;

    float acc[4][4][4];
#pragma unroll
    for (int i = 0; i < 4; i++)
#pragma unroll
        for (int j = 0; j < 4; j++)
#pragma unroll
            for (int q = 0; q < 4; q++) acc[i][j][q] = 0.f;

    const int nch = K >> 5;

    auto load_chunk = [&](int ci) {
        const int s = ci & 1;
        const int k0 = ci << 5;
        const uint32_t st = sb + (uint32_t)s * STAGE;
#pragma unroll
        for (int c = 0; c < 4; c++) {
            const __half* base = (c < 2)
                ? A + (size_t)c * sA + (size_t)bm * K + k0
                : B + (size_t)(c - 2) * sB + (size_t)bn * K + k0;
#pragma unroll
            for (int j = 0; j < 2; j++) {
                const int row = l_row0 + j * 64;
                cp16(st + (uint32_t)(c * TILEB + row * 80 + l_seg * 16),
                     base + (size_t)row * K + l_seg * 8);
            }
        }
        CP_COMMIT();
    };

    load_chunk(0);
    load_chunk(1);

    for (int i = 0; i < nch; i++) {
        CP_WAIT1();
        __syncthreads();
        const uint32_t st = sb + (uint32_t)(i & 1) * STAGE;
#pragma unroll
        for (int kk = 0; kk < 2; kk++) {
            uint32_t bfr[2][4][2];
#pragma unroll
            for (int c = 0; c < 2; c++)
#pragma unroll
                for (int nt = 0; nt < 4; nt++)
                    LDSM_X2(bfr[c][nt][0], bfr[c][nt][1],
                            st + (uint32_t)((2 + c) * TILEB) + (uint32_t)(wn * 80) + b_lo
                               + (uint32_t)(nt * 8 * 80 + kk * 32));
#pragma unroll
            for (int ca = 0; ca < 2; ca++) {
                uint32_t afr[4][4];
#pragma unroll
                for (int mt = 0; mt < 4; mt++)
                    LDSM_X4(afr[mt][0], afr[mt][1], afr[mt][2], afr[mt][3],
                            st + (uint32_t)(ca * TILEB) + (uint32_t)(wm * 80) + a_lo
                               + (uint32_t)(mt * 16 * 80 + kk * 32));
#pragma unroll
                for (int cb = 0; cb < 2; cb++) {
                    if (NTERMS == 4 || ca + cb < 2) {
#pragma unroll
                        for (int mt = 0; mt < 4; mt++)
#pragma unroll
                            for (int nt = 0; nt < 4; nt++)
                                mma_16816(acc[mt][nt], afr[mt], bfr[cb][nt]);
                    }
                }
            }
        }
        __syncthreads();
        if (i + 2 < nch) load_chunk(i + 2);
    }

    // ---------------- epilogue ----------------
    const int r0 = lane >> 2;
    const int c0 = (lane & 3) * 2;
#pragma unroll
    for (int mt = 0; mt < 4; mt++) {
#pragma unroll
        for (int half = 0; half < 2; half++) {
            const int m = bm + wm + mt * 16 + r0 + half * 8;
#pragma unroll
            for (int nt = 0; nt < 4; nt++) {
                const int n = bn + wn + nt * 8 + c0;
                float v0 = acc[mt][nt][half * 2 + 0] * escale;
                float v1 = acc[mt][nt][half * 2 + 1] * escale;
                if (MODE == 0) {
                    const float2 bs = *reinterpret_cast<const float2*>(aux + n);
                    v0 += bs.x; v1 += bs.y;
                    const size_t o = (size_t)m * D_BOT + n;
                    *reinterpret_cast<float2*>(C + o) = make_float2(v0, v1);
                    __half h0, mm0, h1, mm1;
                    split2h(v0, h0, mm0); split2h(v1, h1, mm1);
                    __half2 ph; ph.x = h0; ph.y = h1;
                    __half2 pm; pm.x = mm0; pm.y = mm1;
                    *reinterpret_cast<__half2*>(oc0 + o) = ph;
                    *reinterpret_cast<__half2*>(oc1 + o) = pm;
                } else if (MODE == 2) {
                    const float2 r = *reinterpret_cast<const float2*>(aux + (size_t)m * D_BOT + n);
                    v0 += r.x; v1 += r.y;
                    *reinterpret_cast<float2*>(C + (size_t)m * D_BOT + n) = make_float2(v0, v1);
                } else {
                    if (n < Nout)
                        *reinterpret_cast<float2*>(C + (size_t)m * Nout + n) = make_float2(v0, v1);
                }
            }
        }
    }
}

// ===================== split kernels =====================
__global__ void split2_scale(const float* __restrict__ src, int src_rows, int colshift,
                             float scale,
                             __half* __restrict__ c0, __half* __restrict__ c1, int pad_rows)
{
    const size_t total2 = ((size_t)pad_rows << colshift) >> 1;
    for (size_t i = blockIdx.x * (size_t)blockDim.x + threadIdx.x; i < total2;
         i += (size_t)gridDim.x * blockDim.x) {
        const int row = (int)((i * 2) >> colshift);
        float2 v = (row < src_rows) ? reinterpret_cast<const float2*>(src)[i]
                                    : make_float2(0.f, 0.f);
        v.x *= scale; v.y *= scale;
        __half h0, m0, h1, m1;
        split2h(v.x, h0, m0); split2h(v.y, h1, m1);
        __half2 ph; ph.x = h0; ph.y = h1;
        __half2 pm; pm.x = m0; pm.y = m1;
        reinterpret_cast<__half2*>(c0)[i] = ph;
        reinterpret_cast<__half2*>(c1)[i] = pm;
    }
}

// fused: per-row L2 norm of features_aug, scaled split2 (x * SA4 / ||row||) -> faug2
__global__ void __launch_bounds__(256)
norm_split2(const float* __restrict__ src,
            __half* __restrict__ c0, __half* __restrict__ c1)
{
    const int row = blockIdx.x;
    const int t = threadIdx.x;
    float4 v = reinterpret_cast<const float4*>(src + (size_t)row * D_BOT)[t];
    float s = v.x * v.x + v.y * v.y + v.z * v.z + v.w * v.w;
    __shared__ float sh[256];
    sh[t] = s;
    __syncthreads();
#pragma unroll
    for (int k = 128; k > 0; k >>= 1) {
        if (t < k) sh[t] += sh[t + k];
        __syncthreads();
    }
    const float inv = SA4 / fmaxf(sqrtf(sh[0]), EPSN);
    v.x *= inv; v.y *= inv; v.z *= inv; v.w *= inv;
    const float x[4] = {v.x, v.y, v.z, v.w};
    const size_t base2 = ((size_t)row * D_BOT + t * 4) >> 1;
#pragma unroll
    for (int p = 0; p < 2; p++) {
        __half h0, m0, h1, m1;
        split2h(x[2 * p], h0, m0);
        split2h(x[2 * p + 1], h1, m1);
        __half2 ph; ph.x = h0; ph.y = h1;
        __half2 pm; pm.x = m0; pm.y = m1;
        reinterpret_cast<__half2*>(c0)[base2 + p] = ph;
        reinterpret_cast<__half2*>(c1)[base2 + p] = pm;
    }
}

// centroid [C,D_BOT] -> cT*SW split2, [D_BOT rows, C_PAD cols]
__global__ void transpose_split2(const float* __restrict__ src)
{
    __shared__ float tile[32][33];
    const int bx = blockIdx.x * 32;  // d
    const int by = blockIdx.y * 32;  // c
    const int x = bx + threadIdx.x;
#pragma unroll
    for (int i = 0; i < 32; i += 8) {
        const int c = by + threadIdx.y + i;
        tile[threadIdx.y + i][threadIdx.x] = (c < C_CLS) ? src[(size_t)c * D_BOT + x] * SW : 0.f;
    }
    __syncthreads();
    const int c2 = by + threadIdx.x;
#pragma unroll
    for (int i = 0; i < 32; i += 8) {
        const int d2 = bx + threadIdx.y + i;
        const float v = tile[threadIdx.x][threadIdx.y + i];
        __half h, m;
        split2h(v, h, m);
        const size_t o = (size_t)d2 * C_PAD + c2;
        g_cTs[0][o] = h;
        g_cTs[1][o] = m;
    }
}

// ===================== masked softmax -> sm1 split2 (col-padded, fp16) ==============
__global__ void __launch_bounds__(256)
mask_softmax(const float* __restrict__ logits)
{
    const int row = blockIdx.x;
    const float* x = logits + (size_t)row * C_CLS;
    const int t = threadIdx.x;

    float v[4];
    float lmax = -INFINITY;
    int limax = C_CLS;
#pragma unroll
    for (int i = 0; i < 4; i++) {
        const int j = t + i * 256;
        const float val = (j < C_CLS) ? x[j] : -INFINITY;
        v[i] = val;
        if (val > lmax) { lmax = val; limax = j; }
    }
    __shared__ float smax[256];
    __shared__ int   simax[256];
    smax[t] = lmax; simax[t] = limax;
    __syncthreads();
#pragma unroll
    for (int s = 128; s > 0; s >>= 1) {
        if (t < s) {
            const float o = smax[t + s]; const int oi = simax[t + s];
            if (o > smax[t] || (o == smax[t] && oi < simax[t])) { smax[t] = o; simax[t] = oi; }
        }
        __syncthreads();
    }
    const int predict = simax[0];
    const float rowmax = smax[0];
    const bool priv = (predict >= SHARE);

    float e[4];
    float lsum = 0.f;
#pragma unroll
    for (int i = 0; i < 4; i++) {
        const int j = t + i * 256;
        float ee = 0.f;
        if (j < C_CLS) {
            bool mask;
            if (j == predict) mask = false;
            else if (priv)    mask = true;
            else              mask = (j < SHARE);
            ee = expf((mask ? NEG_FILL : v[i]) - rowmax);
            lsum += ee;
        }
        e[i] = ee;
    }
    __shared__ float ssum[256];
    ssum[t] = lsum;
    __syncthreads();
#pragma unroll
    for (int s = 128; s > 0; s >>= 1) {
        if (t < s) ssum[t] += ssum[t + s];
        __syncthreads();
    }
    const float inv = 1.f / ssum[0];

    __half* o0 = g_sm1s[0] + (size_t)row * C_PAD;
    __half* o1 = g_sm1s[1] + (size_t)row * C_PAD;
#pragma unroll
    for (int i = 0; i < 4; i++) {
        const int j = t + i * 256;
        const float p = (j < C_CLS) ? e[i] * inv : 0.f;
        __half h, m;
        split2h(p, h, m);
        o0[j] = h;
        o1[j] = m;
    }
}

// ===================== plain row softmax =====================
__global__ void __launch_bounds__(256)
softmax_rows(const float* __restrict__ in, float* __restrict__ outp)
{
    const int row = blockIdx.x;
    const float* x = in + (size_t)row * C_CLS;
    const int t = threadIdx.x;
    float v[4];
    float lmax = -INFINITY;
#pragma unroll
    for (int i = 0; i < 4; i++) {
        const int j = t + i * 256;
        v[i] = (j < C_CLS) ? x[j] : -INFINITY;
        lmax = fmaxf(lmax, v[i]);
    }
    __shared__ float sh[256];
    sh[t] = lmax;
    __syncthreads();
#pragma unroll
    for (int s = 128; s > 0; s >>= 1) {
        if (t < s) sh[t] = fmaxf(sh[t], sh[t + s]);
        __syncthreads();
    }
    const float rowmax = sh[0];
    __syncthreads();
    float e[4];
    float lsum = 0.f;
#pragma unroll
    for (int i = 0; i < 4; i++) {
        const int j = t + i * 256;
        float ee = 0.f;
        if (j < C_CLS) { ee = expf(v[i] - rowmax); lsum += ee; }
        e[i] = ee;
    }
    sh[t] = lsum;
    __syncthreads();
#pragma unroll
    for (int s = 128; s > 0; s >>= 1) {
        if (t < s) sh[t] += sh[t + s];
        __syncthreads();
    }
    const float inv = 1.f / sh[0];
    float* o = outp + (size_t)row * C_CLS;
#pragma unroll
    for (int i = 0; i < 4; i++) {
        const int j = t + i * 256;
        if (j < C_CLS) o[j] = e[i] * inv;
    }
}

// =====================================================================
extern "C" void kernel_launch(void* const* d_in, const int* in_sizes, int n_in,
                              void* d_out, int out_size)
{
    const float* features = (const float*)d_in[0];
    const float* W_b      = (const float*)d_in[1];
    const float* b_b      = (const float*)d_in[2];
    const float* W1       = (const float*)d_in[3];
    const float* W2       = (const float*)d_in[4];
    const float* centroid = (const float*)d_in[5];

    float* out = (float*)d_out;
    float* feats        = out;
    float* features_aug = feats + (size_t)B_ROWS * D_BOT;
    float* outputs1     = features_aug + (size_t)B_ROWS * D_BOT;
    float* outputs2     = outputs1 + (size_t)B_ROWS * C_CLS;
    float* softmax_out  = outputs2 + (size_t)B_ROWS * C_CLS;

    __half *feat2, *Wb2, *feats2, *W1s, *sm1s, *cTs, *faug2, *W2s;
    cudaGetSymbolAddress((void**)&feat2,  g_feat2);
    cudaGetSymbolAddress((void**)&Wb2,    g_Wb2);
    cudaGetSymbolAddress((void**)&feats2, g_feats2);
    cudaGetSymbolAddress((void**)&W1s,    g_W1s);
    cudaGetSymbolAddress((void**)&sm1s,   g_sm1s);
    cudaGetSymbolAddress((void**)&cTs,    g_cTs);
    cudaGetSymbolAddress((void**)&faug2,  g_faug2);
    cudaGetSymbolAddress((void**)&W2s,    g_W2s);

    const size_t S_feat  = (size_t)B_ROWS * D_INF;
    const size_t S_Wb    = (size_t)D_BOT  * D_INF;
    const size_t S_feats = (size_t)B_ROWS * D_BOT;
    const size_t S_W1    = (size_t)C_PAD  * D_BOT;
    const size_t S_sm1   = (size_t)B_ROWS * C_PAD;
    const size_t S_cT    = (size_t)D_BOT  * C_PAD;

    constexpr int TILEB = 128 * 80;
    constexpr int SMEMG = 2 * 4 * TILEB;   // 81920 — 2 CTAs/SM
    cudaFuncSetAttribute(gemm_mma<3, 0>, cudaFuncAttributeMaxDynamicSharedMemorySize, SMEMG);
    cudaFuncSetAttribute(gemm_mma<3, 1>, cudaFuncAttributeMaxDynamicSharedMemorySize, SMEMG);
    cudaFuncSetAttribute(gemm_mma<3, 2>, cudaFuncAttributeMaxDynamicSharedMemorySize, SMEMG);
    cudaFuncSetAttribute(gemm_mma<3, 3>, cudaFuncAttributeMaxDynamicSharedMemorySize, SMEMG);

    const dim3 blk(256);
    const dim3 grid8(8, 64);
    const float invSW = 1.0f / SW;

    // splits for GEMM1
    split2_scale<<<1024, blk>>>(features, B_ROWS, 11, 1.0f, feat2, feat2 + S_feat, B_ROWS);
    split2_scale<<<512,  blk>>>(W_b, D_BOT, 11, SW, Wb2, Wb2 + S_Wb, D_BOT);

    // GEMM1: feats = features @ W_b^T + b_b (3-term fp16 split; epilogue emits feats2)
    gemm_mma<3, 0><<<grid8, blk, SMEMG>>>(feat2, S_feat, Wb2, S_Wb, feats, D_INF, D_BOT,
                                          invSW, b_b, feats2, feats2 + S_feats);

    // W1 split
    split2_scale<<<512, blk>>>(W1, C_CLS, 10, SW, W1s, W1s + S_W1, C_PAD);

    // GEMM2: outputs1 = feats @ W1^T (3-term)
    gemm_mma<3, 1><<<grid8, blk, SMEMG>>>(feats2, S_feats, W1s, S_W1, outputs1, D_BOT, C_CLS,
                                          invSW, nullptr, nullptr, nullptr);

    // centroid^T split + masked softmax
    transpose_split2<<<dim3(D_BOT / 32, C_PAD / 32), dim3(32, 8)>>>(centroid);
    mask_softmax<<<B_ROWS, blk>>>(outputs1);

    // GEMM3: features_aug = sm1 @ centroid + feats
    gemm_mma<3, 2><<<grid8, blk, SMEMG>>>(sm1s, S_sm1, cTs, S_cT, features_aug, C_PAD, D_BOT,
                                          invSW, feats, nullptr, nullptr);

    // fused normalize (+*SA4) + split2
    norm_split2<<<B_ROWS, blk>>>(features_aug, faug2, faug2 + S_feats);
    split2_scale<<<512, blk>>>(W2, C_CLS, 10, SW, W2s, W2s + S_W1, C_PAD);

    // GEMM4: outputs2 = x @ W2^T / TEMP   (escale = 20 / (SW*SA4))
    gemm_mma<3, 3><<<grid8, blk, SMEMG>>>(faug2, S_feats, W2s, S_W1, outputs2, D_BOT, C_CLS,
                                          20.0f / (SW * SA4), nullptr, nullptr, nullptr);

    softmax_rows<<<B_ROWS, blk>>>(outputs2, softmax_out);
}

// round 10
// speedup vs baseline: 1.2544x; 1.1133x over previous
#include <cuda_runtime.h>
#include <cuda_fp16.h>
#include <math.h>
#include <stdint.h>

#define B_ROWS   8192
#define D_INF    2048
#define D_BOT    1024
#define C_CLS    1000
#define C_PAD    1024
#define SHARE    500
#define NEG_FILL (-1e9f)
#define EPSN     1e-12f
#define SW       512.0f           // weight pre-scale (keeps fp16 m-components normal)
#define SA4      32.0f            // GEMM4 A pre-scale

// ===================== scratch (static device globals) =====================
__device__ __align__(1024) __half g_feat2 [2][(size_t)B_ROWS * D_INF];
__device__ __align__(1024) __half g_Wb2   [2][(size_t)D_BOT  * D_INF];
__device__ __align__(1024) __half g_feats2[2][(size_t)B_ROWS * D_BOT];
__device__ __align__(1024) __half g_W1s   [2][(size_t)C_PAD  * D_BOT];
__device__ __align__(1024) __half g_sm1h  [(size_t)B_ROWS * C_PAD];   // sm1 h-component only
__device__ __align__(1024) __half g_cTh   [(size_t)D_BOT  * C_PAD];   // centroid^T h-component
__device__ __align__(1024) __half g_faug2 [2][(size_t)B_ROWS * D_BOT];
__device__ __align__(1024) __half g_W2s   [2][(size_t)C_PAD  * D_BOT];

// ===================== helpers =====================
__device__ __forceinline__ uint32_t smem_u32(const void* p) {
    return (uint32_t)__cvta_generic_to_shared(p);
}
__device__ __forceinline__ void cp16(uint32_t sdst, const void* gsrc) {
    asm volatile("cp.async.cg.shared.global [%0], [%1], 16;" :: "r"(sdst), "l"(gsrc));
}
#define CP_COMMIT() asm volatile("cp.async.commit_group;" ::: "memory")
#define CP_WAIT1()  asm volatile("cp.async.wait_group 1;" ::: "memory")

#define LDSM_X4(r0, r1, r2, r3, addr) \
    asm volatile("ldmatrix.sync.aligned.m8n8.x4.shared.b16 {%0,%1,%2,%3}, [%4];" \
        : "=r"(r0), "=r"(r1), "=r"(r2), "=r"(r3) : "r"(addr))
#define LDSM_X2(r0, r1, addr) \
    asm volatile("ldmatrix.sync.aligned.m8n8.x2.shared.b16 {%0,%1}, [%2];" \
        : "=r"(r0), "=r"(r1) : "r"(addr))

__device__ __forceinline__ void mma_16816(float* c, const uint32_t* a, const uint32_t* b) {
    asm volatile(
        "mma.sync.aligned.m16n8k16.row.col.f32.f16.f16.f32 "
        "{%0,%1,%2,%3}, {%4,%5,%6,%7}, {%8,%9}, {%0,%1,%2,%3};"
        : "+f"(c[0]), "+f"(c[1]), "+f"(c[2]), "+f"(c[3])
        : "r"(a[0]), "r"(a[1]), "r"(a[2]), "r"(a[3]), "r"(b[0]), "r"(b[1]));
}

__device__ __forceinline__ void split2h(float x, __half& h, __half& m) {
    h = __float2half_rn(x);
    m = __float2half_rn(x - __half2float(h));
}

// ===================== fp16 split GEMM via mma.sync =====================
// C[8192, Nout](+epilogue) = escale * sum_terms A_c[8192,K] @ B_c[1024,K]^T
// NTERMS=3: 2 components/operand, terms hh+hm+mh.  NTERMS=1: h-only, 1 term.
// block tile 128x128, BK=32, 8 warps (warp tile 64x32), 2-stage cp.async, 2 CTA/SM.
//  MODE 0: v = escale*acc + bias[n]; store stride D_BOT; also split2 -> oc0/oc1
//  MODE 1: v = escale*acc;           store stride Nout, guard n<Nout
//  MODE 2: v = escale*acc + aux[m*D_BOT+n]; store stride D_BOT
//  MODE 3: v = escale*acc;           store stride Nout, guard
template <int NTERMS, int MODE>
__global__ void __launch_bounds__(256, 2)
gemm_mma(const __half* __restrict__ A, size_t sA,
         const __half* __restrict__ B, size_t sB,
         float* __restrict__ C, int K, int Nout, float escale,
         const float* __restrict__ aux,
         __half* __restrict__ oc0, __half* __restrict__ oc1)
{
    extern __shared__ __align__(128) char smem[];
    const uint32_t sb = smem_u32(smem);
    const int tid = threadIdx.x;
    const int wid = tid >> 5;
    const int lane = tid & 31;
    const int bm = blockIdx.y * 128;
    const int bn = blockIdx.x * 128;

    constexpr int NCL = (NTERMS == 1) ? 1 : 2;   // components loaded per operand
    constexpr int TILEB = 128 * 80;              // 10240 B (64B data + 16B pad per row)
    constexpr int STAGE = 2 * NCL * TILEB;

    const int wm = (wid >> 2) * 64;
    const int wn = (wid & 3) * 32;

    const uint32_t a_lo = (uint32_t)((lane & 15) * 80 + (lane >> 4) * 16);
    const uint32_t b_lo = (uint32_t)((lane & 7) * 80 + ((lane >> 3) & 1) * 16);

    const int l_row0 = tid >> 2;
    const int l_seg = tid & 3;

    float acc[4][4][4];
#pragma unroll
    for (int i = 0; i < 4; i++)
#pragma unroll
        for (int j = 0; j < 4; j++)
#pragma unroll
            for (int q = 0; q < 4; q++) acc[i][j][q] = 0.f;

    const int nch = K >> 5;

    auto load_chunk = [&](int ci) {
        const int s = ci & 1;
        const int k0 = ci << 5;
        const uint32_t st = sb + (uint32_t)s * STAGE;
#pragma unroll
        for (int c = 0; c < 2 * NCL; c++) {
            const __half* base = (c < NCL)
                ? A + (size_t)c * sA + (size_t)bm * K + k0
                : B + (size_t)(c - NCL) * sB + (size_t)bn * K + k0;
#pragma unroll
            for (int j = 0; j < 2; j++) {
                const int row = l_row0 + j * 64;
                cp16(st + (uint32_t)(c * TILEB + row * 80 + l_seg * 16),
                     base + (size_t)row * K + l_seg * 8);
            }
        }
        CP_COMMIT();
    };

    load_chunk(0);
    load_chunk(1);

    for (int i = 0; i < nch; i++) {
        CP_WAIT1();
        __syncthreads();
        const uint32_t st = sb + (uint32_t)(i & 1) * STAGE;
#pragma unroll
        for (int kk = 0; kk < 2; kk++) {
            uint32_t bfr[NCL][4][2];
#pragma unroll
            for (int c = 0; c < NCL; c++)
#pragma unroll
                for (int nt = 0; nt < 4; nt++)
                    LDSM_X2(bfr[c][nt][0], bfr[c][nt][1],
                            st + (uint32_t)((NCL + c) * TILEB) + (uint32_t)(wn * 80) + b_lo
                               + (uint32_t)(nt * 8 * 80 + kk * 32));
#pragma unroll
            for (int ca = 0; ca < NCL; ca++) {
                uint32_t afr[4][4];
#pragma unroll
                for (int mt = 0; mt < 4; mt++)
                    LDSM_X4(afr[mt][0], afr[mt][1], afr[mt][2], afr[mt][3],
                            st + (uint32_t)(ca * TILEB) + (uint32_t)(wm * 80) + a_lo
                               + (uint32_t)(mt * 16 * 80 + kk * 32));
#pragma unroll
                for (int cb = 0; cb < NCL; cb++) {
                    if (NTERMS == 1 || ca + cb < 2) {
#pragma unroll
                        for (int mt = 0; mt < 4; mt++)
#pragma unroll
                            for (int nt = 0; nt < 4; nt++)
                                mma_16816(acc[mt][nt], afr[mt], bfr[cb][nt]);
                    }
                }
            }
        }
        __syncthreads();
        if (i + 2 < nch) load_chunk(i + 2);
    }

    // ---------------- epilogue ----------------
    const int r0 = lane >> 2;
    const int c0 = (lane & 3) * 2;
#pragma unroll
    for (int mt = 0; mt < 4; mt++) {
#pragma unroll
        for (int half = 0; half < 2; half++) {
            const int m = bm + wm + mt * 16 + r0 + half * 8;
#pragma unroll
            for (int nt = 0; nt < 4; nt++) {
                const int n = bn + wn + nt * 8 + c0;
                float v0 = acc[mt][nt][half * 2 + 0] * escale;
                float v1 = acc[mt][nt][half * 2 + 1] * escale;
                if (MODE == 0) {
                    const float2 bs = *reinterpret_cast<const float2*>(aux + n);
                    v0 += bs.x; v1 += bs.y;
                    const size_t o = (size_t)m * D_BOT + n;
                    *reinterpret_cast<float2*>(C + o) = make_float2(v0, v1);
                    __half h0, mm0, h1, mm1;
                    split2h(v0, h0, mm0); split2h(v1, h1, mm1);
                    __half2 ph; ph.x = h0; ph.y = h1;
                    __half2 pm; pm.x = mm0; pm.y = mm1;
                    *reinterpret_cast<__half2*>(oc0 + o) = ph;
                    *reinterpret_cast<__half2*>(oc1 + o) = pm;
                } else if (MODE == 2) {
                    const float2 r = *reinterpret_cast<const float2*>(aux + (size_t)m * D_BOT + n);
                    v0 += r.x; v1 += r.y;
                    *reinterpret_cast<float2*>(C + (size_t)m * D_BOT + n) = make_float2(v0, v1);
                } else {
                    if (n < Nout)
                        *reinterpret_cast<float2*>(C + (size_t)m * Nout + n) = make_float2(v0, v1);
                }
            }
        }
    }
}

// ===================== split kernels =====================
__global__ void split2_scale(const float* __restrict__ src, int src_rows, int colshift,
                             float scale,
                             __half* __restrict__ c0, __half* __restrict__ c1, int pad_rows)
{
    const size_t total2 = ((size_t)pad_rows << colshift) >> 1;
    for (size_t i = blockIdx.x * (size_t)blockDim.x + threadIdx.x; i < total2;
         i += (size_t)gridDim.x * blockDim.x) {
        const int row = (int)((i * 2) >> colshift);
        float2 v = (row < src_rows) ? reinterpret_cast<const float2*>(src)[i]
                                    : make_float2(0.f, 0.f);
        v.x *= scale; v.y *= scale;
        __half h0, m0, h1, m1;
        split2h(v.x, h0, m0); split2h(v.y, h1, m1);
        __half2 ph; ph.x = h0; ph.y = h1;
        __half2 pm; pm.x = m0; pm.y = m1;
        reinterpret_cast<__half2*>(c0)[i] = ph;
        reinterpret_cast<__half2*>(c1)[i] = pm;
    }
}

// fused: per-row L2 norm of features_aug, scaled split2 (x * SA4 / ||row||) -> faug2
__global__ void __launch_bounds__(256)
norm_split2(const float* __restrict__ src,
            __half* __restrict__ c0, __half* __restrict__ c1)
{
    const int row = blockIdx.x;
    const int t = threadIdx.x;
    float4 v = reinterpret_cast<const float4*>(src + (size_t)row * D_BOT)[t];
    float s = v.x * v.x + v.y * v.y + v.z * v.z + v.w * v.w;
    __shared__ float sh[256];
    sh[t] = s;
    __syncthreads();
#pragma unroll
    for (int k = 128; k > 0; k >>= 1) {
        if (t < k) sh[t] += sh[t + k];
        __syncthreads();
    }
    const float inv = SA4 / fmaxf(sqrtf(sh[0]), EPSN);
    v.x *= inv; v.y *= inv; v.z *= inv; v.w *= inv;
    const float x[4] = {v.x, v.y, v.z, v.w};
    const size_t base2 = ((size_t)row * D_BOT + t * 4) >> 1;
#pragma unroll
    for (int p = 0; p < 2; p++) {
        __half h0, m0, h1, m1;
        split2h(x[2 * p], h0, m0);
        split2h(x[2 * p + 1], h1, m1);
        __half2 ph; ph.x = h0; ph.y = h1;
        __half2 pm; pm.x = m0; pm.y = m1;
        reinterpret_cast<__half2*>(c0)[base2 + p] = ph;
        reinterpret_cast<__half2*>(c1)[base2 + p] = pm;
    }
}

// centroid [C,D_BOT] -> cT*SW h-component, [D_BOT rows, C_PAD cols]
__global__ void transpose_h(const float* __restrict__ src)
{
    __shared__ float tile[32][33];
    const int bx = blockIdx.x * 32;  // d
    const int by = blockIdx.y * 32;  // c
    const int x = bx + threadIdx.x;
#pragma unroll
    for (int i = 0; i < 32; i += 8) {
        const int c = by + threadIdx.y + i;
        tile[threadIdx.y + i][threadIdx.x] = (c < C_CLS) ? src[(size_t)c * D_BOT + x] * SW : 0.f;
    }
    __syncthreads();
    const int c2 = by + threadIdx.x;
#pragma unroll
    for (int i = 0; i < 32; i += 8) {
        const int d2 = bx + threadIdx.y + i;
        g_cTh[(size_t)d2 * C_PAD + c2] = __float2half_rn(tile[threadIdx.x][threadIdx.y + i]);
    }
}

// ===================== masked softmax -> sm1 h-component (col-padded, fp16) =========
__global__ void __launch_bounds__(256)
mask_softmax(const float* __restrict__ logits)
{
    const int row = blockIdx.x;
    const float* x = logits + (size_t)row * C_CLS;
    const int t = threadIdx.x;

    float v[4];
    float lmax = -INFINITY;
    int limax = C_CLS;
#pragma unroll
    for (int i = 0; i < 4; i++) {
        const int j = t + i * 256;
        const float val = (j < C_CLS) ? x[j] : -INFINITY;
        v[i] = val;
        if (val > lmax) { lmax = val; limax = j; }
    }
    __shared__ float smax[256];
    __shared__ int   simax[256];
    smax[t] = lmax; simax[t] = limax;
    __syncthreads();
#pragma unroll
    for (int s = 128; s > 0; s >>= 1) {
        if (t < s) {
            const float o = smax[t + s]; const int oi = simax[t + s];
            if (o > smax[t] || (o == smax[t] && oi < simax[t])) { smax[t] = o; simax[t] = oi; }
        }
        __syncthreads();
    }
    const int predict = simax[0];
    const float rowmax = smax[0];
    const bool priv = (predict >= SHARE);

    float e[4];
    float lsum = 0.f;
#pragma unroll
    for (int i = 0; i < 4; i++) {
        const int j = t + i * 256;
        float ee = 0.f;
        if (j < C_CLS) {
            bool mask;
            if (j == predict) mask = false;
            else if (priv)    mask = true;
            else              mask = (j < SHARE);
            ee = expf((mask ? NEG_FILL : v[i]) - rowmax);
            lsum += ee;
        }
        e[i] = ee;
    }
    __shared__ float ssum[256];
    ssum[t] = lsum;
    __syncthreads();
#pragma unroll
    for (int s = 128; s > 0; s >>= 1) {
        if (t < s) ssum[t] += ssum[t + s];
        __syncthreads();
    }
    const float inv = 1.f / ssum[0];

    __half* o0 = g_sm1h + (size_t)row * C_PAD;
#pragma unroll
    for (int i = 0; i < 4; i++) {
        const int j = t + i * 256;
        const float p = (j < C_CLS) ? e[i] * inv : 0.f;
        o0[j] = __float2half_rn(p);
    }
}

// ===================== plain row softmax =====================
__global__ void __launch_bounds__(256)
softmax_rows(const float* __restrict__ in, float* __restrict__ outp)
{
    const int row = blockIdx.x;
    const float* x = in + (size_t)row * C_CLS;
    const int t = threadIdx.x;
    float v[4];
    float lmax = -INFINITY;
#pragma unroll
    for (int i = 0; i < 4; i++) {
        const int j = t + i * 256;
        v[i] = (j < C_CLS) ? x[j] : -INFINITY;
        lmax = fmaxf(lmax, v[i]);
    }
    __shared__ float sh[256];
    sh[t] = lmax;
    __syncthreads();
#pragma unroll
    for (int s = 128; s > 0; s >>= 1) {
        if (t < s) sh[t] = fmaxf(sh[t], sh[t + s]);
        __syncthreads();
    }
    const float rowmax = sh[0];
    __syncthreads();
    float e[4];
    float lsum = 0.f;
#pragma unroll
    for (int i = 0; i < 4; i++) {
        const int j = t + i * 256;
        float ee = 0.f;
        if (j < C_CLS) { ee = expf(v[i] - rowmax); lsum += ee; }
        e[i] = ee;
    }
    sh[t] = lsum;
    __syncthreads();
#pragma unroll
    for (int s = 128; s > 0; s >>= 1) {
        if (t < s) sh[t] += sh[t + s];
        __syncthreads();
    }
    const float inv = 1.f / sh[0];
    float* o = outp + (size_t)row * C_CLS;
#pragma unroll
    for (int i = 0; i < 4; i++) {
        const int j = t + i * 256;
        if (j < C_CLS) o[j] = e[i] * inv;
    }
}

// =====================================================================
extern "C" void kernel_launch(void* const* d_in, const int* in_sizes, int n_in,
                              void* d_out, int out_size)
{
    const float* features = (const float*)d_in[0];
    const float* W_b      = (const float*)d_in[1];
    const float* b_b      = (const float*)d_in[2];
    const float* W1       = (const float*)d_in[3];
    const float* W2       = (const float*)d_in[4];
    const float* centroid = (const float*)d_in[5];

    float* out = (float*)d_out;
    float* feats        = out;
    float* features_aug = feats + (size_t)B_ROWS * D_BOT;
    float* outputs1     = features_aug + (size_t)B_ROWS * D_BOT;
    float* outputs2     = outputs1 + (size_t)B_ROWS * C_CLS;
    float* softmax_out  = outputs2 + (size_t)B_ROWS * C_CLS;

    __half *feat2, *Wb2, *feats2, *W1s, *sm1h, *cTh, *faug2, *W2s;
    cudaGetSymbolAddress((void**)&feat2,  g_feat2);
    cudaGetSymbolAddress((void**)&Wb2,    g_Wb2);
    cudaGetSymbolAddress((void**)&feats2, g_feats2);
    cudaGetSymbolAddress((void**)&W1s,    g_W1s);
    cudaGetSymbolAddress((void**)&sm1h,   g_sm1h);
    cudaGetSymbolAddress((void**)&cTh,    g_cTh);
    cudaGetSymbolAddress((void**)&faug2,  g_faug2);
    cudaGetSymbolAddress((void**)&W2s,    g_W2s);

    const size_t S_feat  = (size_t)B_ROWS * D_INF;
    const size_t S_Wb    = (size_t)D_BOT  * D_INF;
    const size_t S_feats = (size_t)B_ROWS * D_BOT;
    const size_t S_W1    = (size_t)C_PAD  * D_BOT;

    constexpr int TILEB = 128 * 80;
    constexpr int SMEMG  = 2 * 4 * TILEB;   // 81920 — NTERMS=3 path, 2 CTAs/SM
    constexpr int SMEMG1 = 2 * 2 * TILEB;   // 40960 — NTERMS=1 path
    cudaFuncSetAttribute(gemm_mma<3, 0>, cudaFuncAttributeMaxDynamicSharedMemorySize, SMEMG);
    cudaFuncSetAttribute(gemm_mma<3, 1>, cudaFuncAttributeMaxDynamicSharedMemorySize, SMEMG);
    cudaFuncSetAttribute(gemm_mma<1, 2>, cudaFuncAttributeMaxDynamicSharedMemorySize, SMEMG1);
    cudaFuncSetAttribute(gemm_mma<3, 3>, cudaFuncAttributeMaxDynamicSharedMemorySize, SMEMG);

    const dim3 blk(256);
    const dim3 grid8(8, 64);
    const float invSW = 1.0f / SW;

    // splits for GEMM1
    split2_scale<<<1024, blk>>>(features, B_ROWS, 11, 1.0f, feat2, feat2 + S_feat, B_ROWS);
    split2_scale<<<512,  blk>>>(W_b, D_BOT, 11, SW, Wb2, Wb2 + S_Wb, D_BOT);

    // GEMM1: feats = features @ W_b^T + b_b (3-term fp16 split; epilogue emits feats2)
    gemm_mma<3, 0><<<grid8, blk, SMEMG>>>(feat2, S_feat, Wb2, S_Wb, feats, D_INF, D_BOT,
                                          invSW, b_b, feats2, feats2 + S_feats);

    // W1 split
    split2_scale<<<512, blk>>>(W1, C_CLS, 10, SW, W1s, W1s + S_W1, C_PAD);

    // GEMM2: outputs1 = feats @ W1^T (3-term)
    gemm_mma<3, 1><<<grid8, blk, SMEMG>>>(feats2, S_feats, W1s, S_W1, outputs1, D_BOT, C_CLS,
                                          invSW, nullptr, nullptr, nullptr);

    // centroid^T h-component + masked softmax (h-only sm1)
    transpose_h<<<dim3(D_BOT / 32, C_PAD / 32), dim3(32, 8)>>>(centroid);
    mask_softmax<<<B_ROWS, blk>>>(outputs1);

    // GEMM3: features_aug = sm1 @ centroid + feats  (1-term h*h — feat_oa is ~2% of feats,
    // so the ~1e-3 relative error on it is ~1e-5 on features_aug)
    gemm_mma<1, 2><<<grid8, blk, SMEMG1>>>(sm1h, 0, cTh, 0, features_aug, C_PAD, D_BOT,
                                           invSW, feats, nullptr, nullptr);

    // fused normalize (+*SA4) + split2
    norm_split2<<<B_ROWS, blk>>>(features_aug, faug2, faug2 + S_feats);
    split2_scale<<<512, blk>>>(W2, C_CLS, 10, SW, W2s, W2s + S_W1, C_PAD);

    // GEMM4: outputs2 = x @ W2^T / TEMP   (escale = 20 / (SW*SA4))
    gemm_mma<3, 3><<<grid8, blk, SMEMG>>>(faug2, S_feats, W2s, S_W1, outputs2, D_BOT, C_CLS,
                                          20.0f / (SW * SA4), nullptr, nullptr, nullptr);

    softmax_rows<<<B_ROWS, blk>>>(outputs2, softmax_out);
}

// round 11
// speedup vs baseline: 1.4029x; 1.1184x over previous
#include <cuda_runtime.h>
#include <cuda_fp16.h>
#include <math.h>
#include <stdint.h>

#define B_ROWS   8192
#define D_INF    2048
#define D_BOT    1024
#define C_CLS    1000
#define C_PAD    1024
#define SHARE    500
#define NEG_FILL (-1e9f)
#define EPSN     1e-12f
#define SW       512.0f           // weight pre-scale (keeps fp16 m-components normal)

// ===================== scratch (static device globals) =====================
__device__ __align__(1024) __half g_feat2 [2][(size_t)B_ROWS * D_INF];
__device__ __align__(1024) __half g_Wb2   [2][(size_t)D_BOT  * D_INF];
__device__ __align__(1024) __half g_feats2[2][(size_t)B_ROWS * D_BOT];
__device__ __align__(1024) __half g_W1s   [2][(size_t)C_PAD  * D_BOT];
__device__ __align__(1024) __half g_sm1h  [(size_t)B_ROWS * C_PAD];   // sm1 h-only
__device__ __align__(1024) __half g_cTh   [(size_t)D_BOT  * C_PAD];   // centroid^T h-only
__device__ __align__(1024) __half g_faugh [(size_t)B_ROWS * D_BOT];   // normalized x, h-only
__device__ __align__(1024) __half g_W2h   [(size_t)C_PAD  * D_BOT];   // W2 h-only

// ===================== helpers =====================
__device__ __forceinline__ uint32_t smem_u32(const void* p) {
    return (uint32_t)__cvta_generic_to_shared(p);
}
__device__ __forceinline__ void cp16(uint32_t sdst, const void* gsrc) {
    asm volatile("cp.async.cg.shared.global [%0], [%1], 16;" :: "r"(sdst), "l"(gsrc));
}
#define CP_COMMIT() asm volatile("cp.async.commit_group;" ::: "memory")
#define CP_WAIT1()  asm volatile("cp.async.wait_group 1;" ::: "memory")

#define LDSM_X4(r0, r1, r2, r3, addr) \
    asm volatile("ldmatrix.sync.aligned.m8n8.x4.shared.b16 {%0,%1,%2,%3}, [%4];" \
        : "=r"(r0), "=r"(r1), "=r"(r2), "=r"(r3) : "r"(addr))
#define LDSM_X2(r0, r1, addr) \
    asm volatile("ldmatrix.sync.aligned.m8n8.x2.shared.b16 {%0,%1}, [%2];" \
        : "=r"(r0), "=r"(r1) : "r"(addr))

__device__ __forceinline__ void mma_16816(float* c, const uint32_t* a, const uint32_t* b) {
    asm volatile(
        "mma.sync.aligned.m16n8k16.row.col.f32.f16.f16.f32 "
        "{%0,%1,%2,%3}, {%4,%5,%6,%7}, {%8,%9}, {%0,%1,%2,%3};"
        : "+f"(c[0]), "+f"(c[1]), "+f"(c[2]), "+f"(c[3])
        : "r"(a[0]), "r"(a[1]), "r"(a[2]), "r"(a[3]), "r"(b[0]), "r"(b[1]));
}

__device__ __forceinline__ void split2h(float x, __half& h, __half& m) {
    h = __float2half_rn(x);
    m = __float2half_rn(x - __half2float(h));
}

// ===================== fp16 split GEMM via mma.sync =====================
// C[8192, Nout](+epilogue) = escale * sum_terms A_c[8192,K] @ B_c[1024,K]^T
// NTERMS=3: 2 components/operand, terms hh+hm+mh.  NTERMS=1: h-only, 1 term.
// block tile 128x128, BK=32, 8 warps (warp tile 64x32), 2-stage cp.async, 2 CTA/SM.
//  MODE 0: v = escale*acc + bias[n]; store stride D_BOT; also split2 -> oc0/oc1
//  MODE 1: v = escale*acc;           store stride Nout, guard n<Nout
//  MODE 2: v = escale*acc + aux[m*D_BOT+n]; store stride D_BOT
//  MODE 3: v = escale*acc;           store stride Nout, guard
template <int NTERMS, int MODE>
__global__ void __launch_bounds__(256, 2)
gemm_mma(const __half* __restrict__ A, size_t sA,
         const __half* __restrict__ B, size_t sB,
         float* __restrict__ C, int K, int Nout, float escale,
         const float* __restrict__ aux,
         __half* __restrict__ oc0, __half* __restrict__ oc1)
{
    extern __shared__ __align__(128) char smem[];
    const uint32_t sb = smem_u32(smem);
    const int tid = threadIdx.x;
    const int wid = tid >> 5;
    const int lane = tid & 31;
    const int bm = blockIdx.y * 128;
    const int bn = blockIdx.x * 128;

    constexpr int NCL = (NTERMS == 1) ? 1 : 2;   // components loaded per operand
    constexpr int TILEB = 128 * 80;              // 10240 B (64B data + 16B pad per row)
    constexpr int STAGE = 2 * NCL * TILEB;

    const int wm = (wid >> 2) * 64;
    const int wn = (wid & 3) * 32;

    const uint32_t a_lo = (uint32_t)((lane & 15) * 80 + (lane >> 4) * 16);
    const uint32_t b_lo = (uint32_t)((lane & 7) * 80 + ((lane >> 3) & 1) * 16);

    const int l_row0 = tid >> 2;
    const int l_seg = tid & 3;

    float acc[4][4][4];
#pragma unroll
    for (int i = 0; i < 4; i++)
#pragma unroll
        for (int j = 0; j < 4; j++)
#pragma unroll
            for (int q = 0; q < 4; q++) acc[i][j][q] = 0.f;

    const int nch = K >> 5;

    auto load_chunk = [&](int ci) {
        const int s = ci & 1;
        const int k0 = ci << 5;
        const uint32_t st = sb + (uint32_t)s * STAGE;
#pragma unroll
        for (int c = 0; c < 2 * NCL; c++) {
            const __half* base = (c < NCL)
                ? A + (size_t)c * sA + (size_t)bm * K + k0
                : B + (size_t)(c - NCL) * sB + (size_t)bn * K + k0;
#pragma unroll
            for (int j = 0; j < 2; j++) {
                const int row = l_row0 + j * 64;
                cp16(st + (uint32_t)(c * TILEB + row * 80 + l_seg * 16),
                     base + (size_t)row * K + l_seg * 8);
            }
        }
        CP_COMMIT();
    };

    load_chunk(0);
    load_chunk(1);

    for (int i = 0; i < nch; i++) {
        CP_WAIT1();
        __syncthreads();
        const uint32_t st = sb + (uint32_t)(i & 1) * STAGE;
#pragma unroll
        for (int kk = 0; kk < 2; kk++) {
            uint32_t bfr[NCL][4][2];
#pragma unroll
            for (int c = 0; c < NCL; c++)
#pragma unroll
                for (int nt = 0; nt < 4; nt++)
                    LDSM_X2(bfr[c][nt][0], bfr[c][nt][1],
                            st + (uint32_t)((NCL + c) * TILEB) + (uint32_t)(wn * 80) + b_lo
                               + (uint32_t)(nt * 8 * 80 + kk * 32));
#pragma unroll
            for (int ca = 0; ca < NCL; ca++) {
                uint32_t afr[4][4];
#pragma unroll
                for (int mt = 0; mt < 4; mt++)
                    LDSM_X4(afr[mt][0], afr[mt][1], afr[mt][2], afr[mt][3],
                            st + (uint32_t)(ca * TILEB) + (uint32_t)(wm * 80) + a_lo
                               + (uint32_t)(mt * 16 * 80 + kk * 32));
#pragma unroll
                for (int cb = 0; cb < NCL; cb++) {
                    if (NTERMS == 1 || ca + cb < 2) {
#pragma unroll
                        for (int mt = 0; mt < 4; mt++)
#pragma unroll
                            for (int nt = 0; nt < 4; nt++)
                                mma_16816(acc[mt][nt], afr[mt], bfr[cb][nt]);
                    }
                }
            }
        }
        __syncthreads();
        if (i + 2 < nch) load_chunk(i + 2);
    }

    // ---------------- epilogue ----------------
    const int r0 = lane >> 2;
    const int c0 = (lane & 3) * 2;
#pragma unroll
    for (int mt = 0; mt < 4; mt++) {
#pragma unroll
        for (int half = 0; half < 2; half++) {
            const int m = bm + wm + mt * 16 + r0 + half * 8;
#pragma unroll
            for (int nt = 0; nt < 4; nt++) {
                const int n = bn + wn + nt * 8 + c0;
                float v0 = acc[mt][nt][half * 2 + 0] * escale;
                float v1 = acc[mt][nt][half * 2 + 1] * escale;
                if (MODE == 0) {
                    const float2 bs = *reinterpret_cast<const float2*>(aux + n);
                    v0 += bs.x; v1 += bs.y;
                    const size_t o = (size_t)m * D_BOT + n;
                    *reinterpret_cast<float2*>(C + o) = make_float2(v0, v1);
                    __half h0, mm0, h1, mm1;
                    split2h(v0, h0, mm0); split2h(v1, h1, mm1);
                    __half2 ph; ph.x = h0; ph.y = h1;
                    __half2 pm; pm.x = mm0; pm.y = mm1;
                    *reinterpret_cast<__half2*>(oc0 + o) = ph;
                    *reinterpret_cast<__half2*>(oc1 + o) = pm;
                } else if (MODE == 2) {
                    const float2 r = *reinterpret_cast<const float2*>(aux + (size_t)m * D_BOT + n);
                    v0 += r.x; v1 += r.y;
                    *reinterpret_cast<float2*>(C + (size_t)m * D_BOT + n) = make_float2(v0, v1);
                } else {
                    if (n < Nout)
                        *reinterpret_cast<float2*>(C + (size_t)m * Nout + n) = make_float2(v0, v1);
                }
            }
        }
    }
}

// ===================== split / convert kernels =====================
__global__ void split2_scale(const float* __restrict__ src, int src_rows, int colshift,
                             float scale,
                             __half* __restrict__ c0, __half* __restrict__ c1, int pad_rows)
{
    const size_t total2 = ((size_t)pad_rows << colshift) >> 1;
    for (size_t i = blockIdx.x * (size_t)blockDim.x + threadIdx.x; i < total2;
         i += (size_t)gridDim.x * blockDim.x) {
        const int row = (int)((i * 2) >> colshift);
        float2 v = (row < src_rows) ? reinterpret_cast<const float2*>(src)[i]
                                    : make_float2(0.f, 0.f);
        v.x *= scale; v.y *= scale;
        __half h0, m0, h1, m1;
        split2h(v.x, h0, m0); split2h(v.y, h1, m1);
        __half2 ph; ph.x = h0; ph.y = h1;
        __half2 pm; pm.x = m0; pm.y = m1;
        reinterpret_cast<__half2*>(c0)[i] = ph;
        reinterpret_cast<__half2*>(c1)[i] = pm;
    }
}

// plain fp16 convert with row padding (h-only)
__global__ void convert_h_pad(const float* __restrict__ src, int src_rows, int colshift,
                              __half* __restrict__ c0, int pad_rows)
{
    const size_t total2 = ((size_t)pad_rows << colshift) >> 1;
    for (size_t i = blockIdx.x * (size_t)blockDim.x + threadIdx.x; i < total2;
         i += (size_t)gridDim.x * blockDim.x) {
        const int row = (int)((i * 2) >> colshift);
        float2 v = (row < src_rows) ? reinterpret_cast<const float2*>(src)[i]
                                    : make_float2(0.f, 0.f);
        __half2 ph; ph.x = __float2half_rn(v.x); ph.y = __float2half_rn(v.y);
        reinterpret_cast<__half2*>(c0)[i] = ph;
    }
}

// fused: per-row L2 norm of features_aug, h-only convert of x = row/||row|| -> faugh
__global__ void __launch_bounds__(256)
norm_h(const float* __restrict__ src, __half* __restrict__ c0)
{
    const int row = blockIdx.x;
    const int t = threadIdx.x;
    float4 v = reinterpret_cast<const float4*>(src + (size_t)row * D_BOT)[t];
    float s = v.x * v.x + v.y * v.y + v.z * v.z + v.w * v.w;
    __shared__ float sh[256];
    sh[t] = s;
    __syncthreads();
#pragma unroll
    for (int k = 128; k > 0; k >>= 1) {
        if (t < k) sh[t] += sh[t + k];
        __syncthreads();
    }
    const float inv = 1.f / fmaxf(sqrtf(sh[0]), EPSN);
    const size_t base2 = ((size_t)row * D_BOT + t * 4) >> 1;
    __half2 p0; p0.x = __float2half_rn(v.x * inv); p0.y = __float2half_rn(v.y * inv);
    __half2 p1; p1.x = __float2half_rn(v.z * inv); p1.y = __float2half_rn(v.w * inv);
    reinterpret_cast<__half2*>(c0)[base2 + 0] = p0;
    reinterpret_cast<__half2*>(c0)[base2 + 1] = p1;
}

// centroid [C,D_BOT] -> cT h-only, [D_BOT rows, C_PAD cols]
__global__ void transpose_h(const float* __restrict__ src)
{
    __shared__ float tile[32][33];
    const int bx = blockIdx.x * 32;  // d
    const int by = blockIdx.y * 32;  // c
    const int x = bx + threadIdx.x;
#pragma unroll
    for (int i = 0; i < 32; i += 8) {
        const int c = by + threadIdx.y + i;
        tile[threadIdx.y + i][threadIdx.x] = (c < C_CLS) ? src[(size_t)c * D_BOT + x] : 0.f;
    }
    __syncthreads();
    const int c2 = by + threadIdx.x;
#pragma unroll
    for (int i = 0; i < 32; i += 8) {
        const int d2 = bx + threadIdx.y + i;
        g_cTh[(size_t)d2 * C_PAD + c2] = __float2half_rn(tile[threadIdx.x][threadIdx.y + i]);
    }
}

// ===================== masked softmax -> sm1 h-only (col-padded, fp16) =========
__global__ void __launch_bounds__(256)
mask_softmax(const float* __restrict__ logits)
{
    const int row = blockIdx.x;
    const float* x = logits + (size_t)row * C_CLS;
    const int t = threadIdx.x;

    float v[4];
    float lmax = -INFINITY;
    int limax = C_CLS;
#pragma unroll
    for (int i = 0; i < 4; i++) {
        const int j = t + i * 256;
        const float val = (j < C_CLS) ? x[j] : -INFINITY;
        v[i] = val;
        if (val > lmax) { lmax = val; limax = j; }
    }
    __shared__ float smax[256];
    __shared__ int   simax[256];
    smax[t] = lmax; simax[t] = limax;
    __syncthreads();
#pragma unroll
    for (int s = 128; s > 0; s >>= 1) {
        if (t < s) {
            const float o = smax[t + s]; const int oi = simax[t + s];
            if (o > smax[t] || (o == smax[t] && oi < simax[t])) { smax[t] = o; simax[t] = oi; }
        }
        __syncthreads();
    }
    const int predict = simax[0];
    const float rowmax = smax[0];
    const bool priv = (predict >= SHARE);

    float e[4];
    float lsum = 0.f;
#pragma unroll
    for (int i = 0; i < 4; i++) {
        const int j = t + i * 256;
        float ee = 0.f;
        if (j < C_CLS) {
            bool mask;
            if (j == predict) mask = false;
            else if (priv)    mask = true;
            else              mask = (j < SHARE);
            ee = expf((mask ? NEG_FILL : v[i]) - rowmax);
            lsum += ee;
        }
        e[i] = ee;
    }
    __shared__ float ssum[256];
    ssum[t] = lsum;
    __syncthreads();
#pragma unroll
    for (int s = 128; s > 0; s >>= 1) {
        if (t < s) ssum[t] += ssum[t + s];
        __syncthreads();
    }
    const float inv = 1.f / ssum[0];

    __half* o0 = g_sm1h + (size_t)row * C_PAD;
#pragma unroll
    for (int i = 0; i < 4; i++) {
        const int j = t + i * 256;
        const float p = (j < C_CLS) ? e[i] * inv : 0.f;
        o0[j] = __float2half_rn(p);
    }
}

// ===================== plain row softmax =====================
__global__ void __launch_bounds__(256)
softmax_rows(const float* __restrict__ in, float* __restrict__ outp)
{
    const int row = blockIdx.x;
    const float* x = in + (size_t)row * C_CLS;
    const int t = threadIdx.x;
    float v[4];
    float lmax = -INFINITY;
#pragma unroll
    for (int i = 0; i < 4; i++) {
        const int j = t + i * 256;
        v[i] = (j < C_CLS) ? x[j] : -INFINITY;
        lmax = fmaxf(lmax, v[i]);
    }
    __shared__ float sh[256];
    sh[t] = lmax;
    __syncthreads();
#pragma unroll
    for (int s = 128; s > 0; s >>= 1) {
        if (t < s) sh[t] = fmaxf(sh[t], sh[t + s]);
        __syncthreads();
    }
    const float rowmax = sh[0];
    __syncthreads();
    float e[4];
    float lsum = 0.f;
#pragma unroll
    for (int i = 0; i < 4; i++) {
        const int j = t + i * 256;
        float ee = 0.f;
        if (j < C_CLS) { ee = expf(v[i] - rowmax); lsum += ee; }
        e[i] = ee;
    }
    sh[t] = lsum;
    __syncthreads();
#pragma unroll
    for (int s = 128; s > 0; s >>= 1) {
        if (t < s) sh[t] += sh[t + s];
        __syncthreads();
    }
    const float inv = 1.f / sh[0];
    float* o = outp + (size_t)row * C_CLS;
#pragma unroll
    for (int i = 0; i < 4; i++) {
        const int j = t + i * 256;
        if (j < C_CLS) o[j] = e[i] * inv;
    }
}

// =====================================================================
extern "C" void kernel_launch(void* const* d_in, const int* in_sizes, int n_in,
                              void* d_out, int out_size)
{
    const float* features = (const float*)d_in[0];
    const float* W_b      = (const float*)d_in[1];
    const float* b_b      = (const float*)d_in[2];
    const float* W1       = (const float*)d_in[3];
    const float* W2       = (const float*)d_in[4];
    const float* centroid = (const float*)d_in[5];

    float* out = (float*)d_out;
    float* feats        = out;
    float* features_aug = feats + (size_t)B_ROWS * D_BOT;
    float* outputs1     = features_aug + (size_t)B_ROWS * D_BOT;
    float* outputs2     = outputs1 + (size_t)B_ROWS * C_CLS;
    float* softmax_out  = outputs2 + (size_t)B_ROWS * C_CLS;

    __half *feat2, *Wb2, *feats2, *W1s, *sm1h, *cTh, *faugh, *W2h;
    cudaGetSymbolAddress((void**)&feat2,  g_feat2);
    cudaGetSymbolAddress((void**)&Wb2,    g_Wb2);
    cudaGetSymbolAddress((void**)&feats2, g_feats2);
    cudaGetSymbolAddress((void**)&W1s,    g_W1s);
    cudaGetSymbolAddress((void**)&sm1h,   g_sm1h);
    cudaGetSymbolAddress((void**)&cTh,    g_cTh);
    cudaGetSymbolAddress((void**)&faugh,  g_faugh);
    cudaGetSymbolAddress((void**)&W2h,    g_W2h);

    const size_t S_feat  = (size_t)B_ROWS * D_INF;
    const size_t S_Wb    = (size_t)D_BOT  * D_INF;
    const size_t S_feats = (size_t)B_ROWS * D_BOT;
    const size_t S_W1    = (size_t)C_PAD  * D_BOT;

    constexpr int TILEB = 128 * 80;
    constexpr int SMEMG  = 2 * 4 * TILEB;   // 81920 — NTERMS=3 path, 2 CTAs/SM
    constexpr int SMEMG1 = 2 * 2 * TILEB;   // 40960 — NTERMS=1 path
    cudaFuncSetAttribute(gemm_mma<3, 0>, cudaFuncAttributeMaxDynamicSharedMemorySize, SMEMG);
    cudaFuncSetAttribute(gemm_mma<3, 1>, cudaFuncAttributeMaxDynamicSharedMemorySize, SMEMG);
    cudaFuncSetAttribute(gemm_mma<1, 2>, cudaFuncAttributeMaxDynamicSharedMemorySize, SMEMG1);
    cudaFuncSetAttribute(gemm_mma<1, 3>, cudaFuncAttributeMaxDynamicSharedMemorySize, SMEMG1);

    const dim3 blk(256);
    const dim3 grid8(8, 64);
    const float invSW = 1.0f / SW;

    // splits for GEMM1
    split2_scale<<<1024, blk>>>(features, B_ROWS, 11, 1.0f, feat2, feat2 + S_feat, B_ROWS);
    split2_scale<<<512,  blk>>>(W_b, D_BOT, 11, SW, Wb2, Wb2 + S_Wb, D_BOT);

    // GEMM1: feats = features @ W_b^T + b_b (3-term fp16 split; epilogue emits feats2)
    gemm_mma<3, 0><<<grid8, blk, SMEMG>>>(feat2, S_feat, Wb2, S_Wb, feats, D_INF, D_BOT,
                                          invSW, b_b, feats2, feats2 + S_feats);

    // W1 split
    split2_scale<<<512, blk>>>(W1, C_CLS, 10, SW, W1s, W1s + S_W1, C_PAD);

    // GEMM2: outputs1 = feats @ W1^T (3-term — argmax-critical, do not cut)
    gemm_mma<3, 1><<<grid8, blk, SMEMG>>>(feats2, S_feats, W1s, S_W1, outputs1, D_BOT, C_CLS,
                                          invSW, nullptr, nullptr, nullptr);

    // centroid^T h-only + masked softmax (h-only sm1)
    transpose_h<<<dim3(D_BOT / 32, C_PAD / 32), dim3(32, 8)>>>(centroid);
    mask_softmax<<<B_ROWS, blk>>>(outputs1);

    // GEMM3: features_aug = sm1 @ centroid + feats  (1-term h*h; feat_oa ~2% of feats)
    gemm_mma<1, 2><<<grid8, blk, SMEMG1>>>(sm1h, 0, cTh, 0, features_aug, C_PAD, D_BOT,
                                           1.0f, feats, nullptr, nullptr);

    // fused normalize + h-only convert; W2 h-only convert
    norm_h<<<B_ROWS, blk>>>(features_aug, faugh);
    convert_h_pad<<<512, blk>>>(W2, C_CLS, 10, W2h, C_PAD);

    // GEMM4: outputs2 = x @ W2^T / TEMP  (1-term h*h: x unit-norm, err ~2e-4 rel << 1e-3)
    gemm_mma<1, 3><<<grid8, blk, SMEMG1>>>(faugh, 0, W2h, 0, outputs2, D_BOT, C_CLS,
                                           20.0f, nullptr, nullptr, nullptr);

    softmax_rows<<<B_ROWS, blk>>>(outputs2, softmax_out);
}

// round 12
// speedup vs baseline: 1.4623x; 1.0424x over previous
#include <cuda_runtime.h>
#include <cuda_fp16.h>
#include <math.h>
#include <stdint.h>

#define B_ROWS   8192
#define D_INF    2048
#define D_BOT    1024
#define C_CLS    1000
#define C_PAD    1024
#define SHARE    500
#define NEG_FILL (-1e9f)
#define EPSN     1e-12f
#define SW       512.0f           // weight pre-scale (keeps fp16 m-components normal)

// ===================== scratch (static device globals) =====================
__device__ __align__(1024) __half g_feat2 [2][(size_t)B_ROWS * D_INF];
__device__ __align__(1024) __half g_Wb2   [2][(size_t)D_BOT  * D_INF];
__device__ __align__(1024) __half g_feats2[2][(size_t)B_ROWS * D_BOT];
__device__ __align__(1024) __half g_W1s   [2][(size_t)C_PAD  * D_BOT];
__device__ __align__(1024) __half g_sm1h  [(size_t)B_ROWS * C_PAD];   // sm1 h-only
__device__ __align__(1024) __half g_cTh   [(size_t)D_BOT  * C_PAD];   // centroid^T h-only
__device__ __align__(1024) __half g_faugh [(size_t)B_ROWS * D_BOT];   // normalized x, h-only
__device__ __align__(1024) __half g_W2h   [(size_t)C_PAD  * D_BOT];   // W2 h-only

// ===================== helpers =====================
__device__ __forceinline__ uint32_t smem_u32(const void* p) {
    return (uint32_t)__cvta_generic_to_shared(p);
}
__device__ __forceinline__ void cp16(uint32_t sdst, const void* gsrc) {
    asm volatile("cp.async.cg.shared.global [%0], [%1], 16;" :: "r"(sdst), "l"(gsrc));
}
#define CP_COMMIT() asm volatile("cp.async.commit_group;" ::: "memory")
#define CP_WAIT1()  asm volatile("cp.async.wait_group 1;" ::: "memory")

#define LDSM_X4(r0, r1, r2, r3, addr) \
    asm volatile("ldmatrix.sync.aligned.m8n8.x4.shared.b16 {%0,%1,%2,%3}, [%4];" \
        : "=r"(r0), "=r"(r1), "=r"(r2), "=r"(r3) : "r"(addr))
#define LDSM_X2(r0, r1, addr) \
    asm volatile("ldmatrix.sync.aligned.m8n8.x2.shared.b16 {%0,%1}, [%2];" \
        : "=r"(r0), "=r"(r1) : "r"(addr))

__device__ __forceinline__ void mma_16816(float* c, const uint32_t* a, const uint32_t* b) {
    asm volatile(
        "mma.sync.aligned.m16n8k16.row.col.f32.f16.f16.f32 "
        "{%0,%1,%2,%3}, {%4,%5,%6,%7}, {%8,%9}, {%0,%1,%2,%3};"
        : "+f"(c[0]), "+f"(c[1]), "+f"(c[2]), "+f"(c[3])
        : "r"(a[0]), "r"(a[1]), "r"(a[2]), "r"(a[3]), "r"(b[0]), "r"(b[1]));
}

__device__ __forceinline__ void split2h(float x, __half& h, __half& m) {
    h = __float2half_rn(x);
    m = __float2half_rn(x - __half2float(h));
}

// ===================== fp16 split GEMM via mma.sync =====================
// C[8192, Nout](+epilogue) = escale * sum_terms A_c[8192,K] @ B_c[1024,K]^T
// NTERMS=3: 2 components/operand, terms hh+hm+mh.  NTERMS=1: h-only, 1 term.
// block tile 128x128, BK=32, 8 warps (warp tile 64x32), 2-stage cp.async, 2 CTA/SM.
//  MODE 0: v = escale*acc + bias[n]; store stride D_BOT; also split2 -> oc0/oc1
//  MODE 1: v = escale*acc;           store stride Nout, guard n<Nout
//  MODE 2: v = escale*acc + aux[m*D_BOT+n]; store stride D_BOT
//  MODE 3: v = escale*acc;           store stride Nout, guard
template <int NTERMS, int MODE>
__global__ void __launch_bounds__(256, 2)
gemm_mma(const __half* __restrict__ A, size_t sA,
         const __half* __restrict__ B, size_t sB,
         float* __restrict__ C, int K, int Nout, float escale,
         const float* __restrict__ aux,
         __half* __restrict__ oc0, __half* __restrict__ oc1)
{
    extern __shared__ __align__(128) char smem[];
    const uint32_t sb = smem_u32(smem);
    const int tid = threadIdx.x;
    const int wid = tid >> 5;
    const int lane = tid & 31;
    const int bm = blockIdx.y * 128;
    const int bn = blockIdx.x * 128;

    constexpr int NCL = (NTERMS == 1) ? 1 : 2;   // components loaded per operand
    constexpr int TILEB = 128 * 80;              // 10240 B (64B data + 16B pad per row)
    constexpr int STAGE = 2 * NCL * TILEB;

    const int wm = (wid >> 2) * 64;
    const int wn = (wid & 3) * 32;

    const uint32_t a_lo = (uint32_t)((lane & 15) * 80 + (lane >> 4) * 16);
    const uint32_t b_lo = (uint32_t)((lane & 7) * 80 + ((lane >> 3) & 1) * 16);

    const int l_row0 = tid >> 2;
    const int l_seg = tid & 3;

    float acc[4][4][4];
#pragma unroll
    for (int i = 0; i < 4; i++)
#pragma unroll
        for (int j = 0; j < 4; j++)
#pragma unroll
            for (int q = 0; q < 4; q++) acc[i][j][q] = 0.f;

    const int nch = K >> 5;

    auto load_chunk = [&](int ci) {
        const int s = ci & 1;
        const int k0 = ci << 5;
        const uint32_t st = sb + (uint32_t)s * STAGE;
#pragma unroll
        for (int c = 0; c < 2 * NCL; c++) {
            const __half* base = (c < NCL)
                ? A + (size_t)c * sA + (size_t)bm * K + k0
                : B + (size_t)(c - NCL) * sB + (size_t)bn * K + k0;
#pragma unroll
            for (int j = 0; j < 2; j++) {
                const int row = l_row0 + j * 64;
                cp16(st + (uint32_t)(c * TILEB + row * 80 + l_seg * 16),
                     base + (size_t)row * K + l_seg * 8);
            }
        }
        CP_COMMIT();
    };

    load_chunk(0);
    load_chunk(1);

    for (int i = 0; i < nch; i++) {
        CP_WAIT1();
        __syncthreads();
        const uint32_t st = sb + (uint32_t)(i & 1) * STAGE;
#pragma unroll
        for (int kk = 0; kk < 2; kk++) {
            uint32_t bfr[NCL][4][2];
#pragma unroll
            for (int c = 0; c < NCL; c++)
#pragma unroll
                for (int nt = 0; nt < 4; nt++)
                    LDSM_X2(bfr[c][nt][0], bfr[c][nt][1],
                            st + (uint32_t)((NCL + c) * TILEB) + (uint32_t)(wn * 80) + b_lo
                               + (uint32_t)(nt * 8 * 80 + kk * 32));
#pragma unroll
            for (int ca = 0; ca < NCL; ca++) {
                uint32_t afr[4][4];
#pragma unroll
                for (int mt = 0; mt < 4; mt++)
                    LDSM_X4(afr[mt][0], afr[mt][1], afr[mt][2], afr[mt][3],
                            st + (uint32_t)(ca * TILEB) + (uint32_t)(wm * 80) + a_lo
                               + (uint32_t)(mt * 16 * 80 + kk * 32));
#pragma unroll
                for (int cb = 0; cb < NCL; cb++) {
                    if (NTERMS == 1 || ca + cb < 2) {
#pragma unroll
                        for (int mt = 0; mt < 4; mt++)
#pragma unroll
                            for (int nt = 0; nt < 4; nt++)
                                mma_16816(acc[mt][nt], afr[mt], bfr[cb][nt]);
                    }
                }
            }
        }
        __syncthreads();
        if (i + 2 < nch) load_chunk(i + 2);
    }

    // ---------------- epilogue ----------------
    const int r0 = lane >> 2;
    const int c0 = (lane & 3) * 2;
#pragma unroll
    for (int mt = 0; mt < 4; mt++) {
#pragma unroll
        for (int half = 0; half < 2; half++) {
            const int m = bm + wm + mt * 16 + r0 + half * 8;
#pragma unroll
            for (int nt = 0; nt < 4; nt++) {
                const int n = bn + wn + nt * 8 + c0;
                float v0 = acc[mt][nt][half * 2 + 0] * escale;
                float v1 = acc[mt][nt][half * 2 + 1] * escale;
                if (MODE == 0) {
                    const float2 bs = *reinterpret_cast<const float2*>(aux + n);
                    v0 += bs.x; v1 += bs.y;
                    const size_t o = (size_t)m * D_BOT + n;
                    *reinterpret_cast<float2*>(C + o) = make_float2(v0, v1);
                    __half h0, mm0, h1, mm1;
                    split2h(v0, h0, mm0); split2h(v1, h1, mm1);
                    __half2 ph; ph.x = h0; ph.y = h1;
                    __half2 pm; pm.x = mm0; pm.y = mm1;
                    *reinterpret_cast<__half2*>(oc0 + o) = ph;
                    *reinterpret_cast<__half2*>(oc1 + o) = pm;
                } else if (MODE == 2) {
                    const float2 r = *reinterpret_cast<const float2*>(aux + (size_t)m * D_BOT + n);
                    v0 += r.x; v1 += r.y;
                    *reinterpret_cast<float2*>(C + (size_t)m * D_BOT + n) = make_float2(v0, v1);
                } else {
                    if (n < Nout)
                        *reinterpret_cast<float2*>(C + (size_t)m * Nout + n) = make_float2(v0, v1);
                }
            }
        }
    }
}

// ===================== split / convert kernels =====================
__global__ void split2_scale(const float* __restrict__ src, int src_rows, int colshift,
                             float scale,
                             __half* __restrict__ c0, __half* __restrict__ c1, int pad_rows)
{
    const size_t total2 = ((size_t)pad_rows << colshift) >> 1;
    for (size_t i = blockIdx.x * (size_t)blockDim.x + threadIdx.x; i < total2;
         i += (size_t)gridDim.x * blockDim.x) {
        const int row = (int)((i * 2) >> colshift);
        float2 v = (row < src_rows) ? reinterpret_cast<const float2*>(src)[i]
                                    : make_float2(0.f, 0.f);
        v.x *= scale; v.y *= scale;
        __half h0, m0, h1, m1;
        split2h(v.x, h0, m0); split2h(v.y, h1, m1);
        __half2 ph; ph.x = h0; ph.y = h1;
        __half2 pm; pm.x = m0; pm.y = m1;
        reinterpret_cast<__half2*>(c0)[i] = ph;
        reinterpret_cast<__half2*>(c1)[i] = pm;
    }
}

// plain fp16 convert with row padding (h-only)
__global__ void convert_h_pad(const float* __restrict__ src, int src_rows, int colshift,
                              __half* __restrict__ c0, int pad_rows)
{
    const size_t total2 = ((size_t)pad_rows << colshift) >> 1;
    for (size_t i = blockIdx.x * (size_t)blockDim.x + threadIdx.x; i < total2;
         i += (size_t)gridDim.x * blockDim.x) {
        const int row = (int)((i * 2) >> colshift);
        float2 v = (row < src_rows) ? reinterpret_cast<const float2*>(src)[i]
                                    : make_float2(0.f, 0.f);
        __half2 ph; ph.x = __float2half_rn(v.x); ph.y = __float2half_rn(v.y);
        reinterpret_cast<__half2*>(c0)[i] = ph;
    }
}

// fused warp-per-row: L2 norm of features_aug row, h-only convert of x = row/||row||
// 8 warps/block, one row per warp; no shared memory, no block sync.
__global__ void __launch_bounds__(256)
norm_h(const float* __restrict__ src, __half* __restrict__ c0)
{
    const int warp = threadIdx.x >> 5;
    const int lane = threadIdx.x & 31;
    const int row = blockIdx.x * 8 + warp;
    const float4* xr = reinterpret_cast<const float4*>(src + (size_t)row * D_BOT);

    float4 vv[8];
    float s = 0.f;
#pragma unroll
    for (int i = 0; i < 8; i++) {
        vv[i] = xr[lane + i * 32];
        s += vv[i].x * vv[i].x + vv[i].y * vv[i].y + vv[i].z * vv[i].z + vv[i].w * vv[i].w;
    }
#pragma unroll
    for (int off = 16; off > 0; off >>= 1)
        s += __shfl_xor_sync(0xFFFFFFFFu, s, off);
    const float inv = 1.f / fmaxf(sqrtf(s), EPSN);

    uint2* outp = reinterpret_cast<uint2*>(c0 + (size_t)row * D_BOT);
#pragma unroll
    for (int i = 0; i < 8; i++) {
        __half2 p0; p0.x = __float2half_rn(vv[i].x * inv); p0.y = __float2half_rn(vv[i].y * inv);
        __half2 p1; p1.x = __float2half_rn(vv[i].z * inv); p1.y = __float2half_rn(vv[i].w * inv);
        uint2 pk;
        pk.x = *reinterpret_cast<uint32_t*>(&p0);
        pk.y = *reinterpret_cast<uint32_t*>(&p1);
        outp[lane + i * 32] = pk;
    }
}

// centroid [C,D_BOT] -> cT h-only, [D_BOT rows, C_PAD cols]
__global__ void transpose_h(const float* __restrict__ src)
{
    __shared__ float tile[32][33];
    const int bx = blockIdx.x * 32;  // d
    const int by = blockIdx.y * 32;  // c
    const int x = bx + threadIdx.x;
#pragma unroll
    for (int i = 0; i < 32; i += 8) {
        const int c = by + threadIdx.y + i;
        tile[threadIdx.y + i][threadIdx.x] = (c < C_CLS) ? src[(size_t)c * D_BOT + x] : 0.f;
    }
    __syncthreads();
    const int c2 = by + threadIdx.x;
#pragma unroll
    for (int i = 0; i < 32; i += 8) {
        const int d2 = bx + threadIdx.y + i;
        g_cTh[(size_t)d2 * C_PAD + c2] = __float2half_rn(tile[threadIdx.x][threadIdx.y + i]);
    }
}

// ============ warp-per-row masked softmax -> sm1 h-only (col-padded, fp16) ==========
// 8 warps/block, one row per warp. Paired-element layout: lane handles (j, j+1),
// j = i*64 + lane*2, i ascending -> per-lane first occurrence kept; cross-lane
// ties resolved by explicit min-index. Writes __half2 (8B/lane, 256B/warp-op).
__global__ void __launch_bounds__(256)
mask_softmax(const float* __restrict__ logits)
{
    const int warp = threadIdx.x >> 5;
    const int lane = threadIdx.x & 31;
    const int row = blockIdx.x * 8 + warp;
    const float* x = logits + (size_t)row * C_CLS;

    float v[32];
    float lmax = -INFINITY;
    int limax = C_PAD;
#pragma unroll
    for (int i = 0; i < 16; i++) {
        const int j = i * 64 + lane * 2;
        const float a = (j < C_CLS) ? x[j] : -INFINITY;
        const float b = (j + 1 < C_CLS) ? x[j + 1] : -INFINITY;
        v[2 * i] = a; v[2 * i + 1] = b;
        if (a > lmax) { lmax = a; limax = j; }
        if (b > lmax) { lmax = b; limax = j + 1; }
    }
#pragma unroll
    for (int off = 16; off > 0; off >>= 1) {
        const float ov = __shfl_xor_sync(0xFFFFFFFFu, lmax, off);
        const int   oi = __shfl_xor_sync(0xFFFFFFFFu, limax, off);
        if (ov > lmax || (ov == lmax && oi < limax)) { lmax = ov; limax = oi; }
    }
    const int predict = limax;
    const float rowmax = lmax;
    const bool priv = (predict >= SHARE);

    float e[32];
    float lsum = 0.f;
#pragma unroll
    for (int i = 0; i < 32; i++) {
        const int j = (i >> 1) * 64 + lane * 2 + (i & 1);
        float ee = 0.f;
        if (j < C_CLS) {
            bool mask;
            if (j == predict) mask = false;
            else if (priv)    mask = true;
            else              mask = (j < SHARE);
            ee = expf((mask ? NEG_FILL : v[i]) - rowmax);
            lsum += ee;
        }
        e[i] = ee;
    }
#pragma unroll
    for (int off = 16; off > 0; off >>= 1)
        lsum += __shfl_xor_sync(0xFFFFFFFFu, lsum, off);
    const float inv = 1.f / lsum;

    __half* o0 = g_sm1h + (size_t)row * C_PAD;
#pragma unroll
    for (int i = 0; i < 16; i++) {
        const int j = i * 64 + lane * 2;   // covers 0..1022; pad cols get e=0
        __half2 p;
        p.x = __float2half_rn(e[2 * i] * inv);
        p.y = __float2half_rn(e[2 * i + 1] * inv);
        *reinterpret_cast<__half2*>(o0 + j) = p;
    }
}

// ===================== warp-per-row plain softmax =====================
__global__ void __launch_bounds__(256)
softmax_rows(const float* __restrict__ in, float* __restrict__ outp)
{
    const int warp = threadIdx.x >> 5;
    const int lane = threadIdx.x & 31;
    const int row = blockIdx.x * 8 + warp;
    const float* x = in + (size_t)row * C_CLS;

    float v[32];
    float lmax = -INFINITY;
#pragma unroll
    for (int i = 0; i < 16; i++) {
        const int j = i * 64 + lane * 2;
        v[2 * i]     = (j < C_CLS) ? x[j] : -INFINITY;
        v[2 * i + 1] = (j + 1 < C_CLS) ? x[j + 1] : -INFINITY;
        lmax = fmaxf(lmax, fmaxf(v[2 * i], v[2 * i + 1]));
    }
#pragma unroll
    for (int off = 16; off > 0; off >>= 1)
        lmax = fmaxf(lmax, __shfl_xor_sync(0xFFFFFFFFu, lmax, off));

    float e[32];
    float lsum = 0.f;
#pragma unroll
    for (int i = 0; i < 32; i++) {
        const int j = (i >> 1) * 64 + lane * 2 + (i & 1);
        float ee = 0.f;
        if (j < C_CLS) { ee = expf(v[i] - lmax); lsum += ee; }
        e[i] = ee;
    }
#pragma unroll
    for (int off = 16; off > 0; off >>= 1)
        lsum += __shfl_xor_sync(0xFFFFFFFFu, lsum, off);
    const float inv = 1.f / lsum;

    float* o = outp + (size_t)row * C_CLS;
#pragma unroll
    for (int i = 0; i < 16; i++) {
        const int j = i * 64 + lane * 2;
        if (j + 1 < C_CLS) {
            *reinterpret_cast<float2*>(o + j) = make_float2(e[2 * i] * inv, e[2 * i + 1] * inv);
        } else if (j < C_CLS) {
            o[j] = e[2 * i] * inv;
        }
    }
}

// =====================================================================
extern "C" void kernel_launch(void* const* d_in, const int* in_sizes, int n_in,
                              void* d_out, int out_size)
{
    const float* features = (const float*)d_in[0];
    const float* W_b      = (const float*)d_in[1];
    const float* b_b      = (const float*)d_in[2];
    const float* W1       = (const float*)d_in[3];
    const float* W2       = (const float*)d_in[4];
    const float* centroid = (const float*)d_in[5];

    float* out = (float*)d_out;
    float* feats        = out;
    float* features_aug = feats + (size_t)B_ROWS * D_BOT;
    float* outputs1     = features_aug + (size_t)B_ROWS * D_BOT;
    float* outputs2     = outputs1 + (size_t)B_ROWS * C_CLS;
    float* softmax_out  = outputs2 + (size_t)B_ROWS * C_CLS;

    __half *feat2, *Wb2, *feats2, *W1s, *sm1h, *cTh, *faugh, *W2h;
    cudaGetSymbolAddress((void**)&feat2,  g_feat2);
    cudaGetSymbolAddress((void**)&Wb2,    g_Wb2);
    cudaGetSymbolAddress((void**)&feats2, g_feats2);
    cudaGetSymbolAddress((void**)&W1s,    g_W1s);
    cudaGetSymbolAddress((void**)&sm1h,   g_sm1h);
    cudaGetSymbolAddress((void**)&cTh,    g_cTh);
    cudaGetSymbolAddress((void**)&faugh,  g_faugh);
    cudaGetSymbolAddress((void**)&W2h,    g_W2h);

    const size_t S_feat  = (size_t)B_ROWS * D_INF;
    const size_t S_Wb    = (size_t)D_BOT  * D_INF;
    const size_t S_feats = (size_t)B_ROWS * D_BOT;
    const size_t S_W1    = (size_t)C_PAD  * D_BOT;

    constexpr int TILEB = 128 * 80;
    constexpr int SMEMG  = 2 * 4 * TILEB;   // 81920 — NTERMS=3 path, 2 CTAs/SM
    constexpr int SMEMG1 = 2 * 2 * TILEB;   // 40960 — NTERMS=1 path
    cudaFuncSetAttribute(gemm_mma<3, 0>, cudaFuncAttributeMaxDynamicSharedMemorySize, SMEMG);
    cudaFuncSetAttribute(gemm_mma<3, 1>, cudaFuncAttributeMaxDynamicSharedMemorySize, SMEMG);
    cudaFuncSetAttribute(gemm_mma<1, 2>, cudaFuncAttributeMaxDynamicSharedMemorySize, SMEMG1);
    cudaFuncSetAttribute(gemm_mma<1, 3>, cudaFuncAttributeMaxDynamicSharedMemorySize, SMEMG1);

    const dim3 blk(256);
    const dim3 grid8(8, 64);
    const float invSW = 1.0f / SW;

    // splits for GEMM1
    split2_scale<<<1024, blk>>>(features, B_ROWS, 11, 1.0f, feat2, feat2 + S_feat, B_ROWS);
    split2_scale<<<512,  blk>>>(W_b, D_BOT, 11, SW, Wb2, Wb2 + S_Wb, D_BOT);

    // GEMM1: feats = features @ W_b^T + b_b (3-term fp16 split; epilogue emits feats2)
    gemm_mma<3, 0><<<grid8, blk, SMEMG>>>(feat2, S_feat, Wb2, S_Wb, feats, D_INF, D_BOT,
                                          invSW, b_b, feats2, feats2 + S_feats);

    // W1 split
    split2_scale<<<512, blk>>>(W1, C_CLS, 10, SW, W1s, W1s + S_W1, C_PAD);

    // GEMM2: outputs1 = feats @ W1^T (3-term — argmax-critical, do not cut)
    gemm_mma<3, 1><<<grid8, blk, SMEMG>>>(feats2, S_feats, W1s, S_W1, outputs1, D_BOT, C_CLS,
                                          invSW, nullptr, nullptr, nullptr);

    // centroid^T h-only + masked softmax (warp-per-row, h-only sm1)
    transpose_h<<<dim3(D_BOT / 32, C_PAD / 32), dim3(32, 8)>>>(centroid);
    mask_softmax<<<B_ROWS / 8, blk>>>(outputs1);

    // GEMM3: features_aug = sm1 @ centroid + feats  (1-term h*h; feat_oa ~2% of feats)
    gemm_mma<1, 2><<<grid8, blk, SMEMG1>>>(sm1h, 0, cTh, 0, features_aug, C_PAD, D_BOT,
                                           1.0f, feats, nullptr, nullptr);

    // fused warp-per-row normalize + h-only convert; W2 h-only convert
    norm_h<<<B_ROWS / 8, blk>>>(features_aug, faugh);
    convert_h_pad<<<512, blk>>>(W2, C_CLS, 10, W2h, C_PAD);

    // GEMM4: outputs2 = x @ W2^T / TEMP  (1-term h*h: x unit-norm, err ~2e-4 rel << 1e-3)
    gemm_mma<1, 3><<<grid8, blk, SMEMG1>>>(faugh, 0, W2h, 0, outputs2, D_BOT, C_CLS,
                                           20.0f, nullptr, nullptr, nullptr);

    softmax_rows<<<B_ROWS / 8, blk>>>(outputs2, softmax_out);
}

// round 13
// speedup vs baseline: 1.4833x; 1.0143x over previous
#include <cuda_runtime.h>
#include <cuda_fp16.h>
#include <math.h>
#include <stdint.h>

#define B_ROWS   8192
#define D_INF    2048
#define D_BOT    1024
#define C_CLS    1000
#define C_PAD    1024
#define SHARE    500
#define NEG_FILL (-1e9f)
#define EPSN     1e-12f
#define SW       512.0f           // weight pre-scale (keeps fp16 m-components normal)

// ===================== scratch (static device globals) =====================
__device__ __align__(1024) __half g_feat2 [2][(size_t)B_ROWS * D_INF];
__device__ __align__(1024) __half g_Wb2   [2][(size_t)D_BOT  * D_INF];
__device__ __align__(1024) __half g_feats2[2][(size_t)B_ROWS * D_BOT];
__device__ __align__(1024) __half g_W1s   [2][(size_t)C_PAD  * D_BOT];
__device__ __align__(1024) __half g_sm1h  [(size_t)B_ROWS * C_PAD];   // sm1 h-only
__device__ __align__(1024) __half g_cTh   [(size_t)D_BOT  * C_PAD];   // centroid^T h-only
__device__ __align__(1024) __half g_faugh [(size_t)B_ROWS * D_BOT];   // normalized x, h-only
__device__ __align__(1024) __half g_W2h   [(size_t)C_PAD  * D_BOT];   // W2 h-only

// ===================== helpers =====================
__device__ __forceinline__ uint32_t smem_u32(const void* p) {
    return (uint32_t)__cvta_generic_to_shared(p);
}
__device__ __forceinline__ void cp16(uint32_t sdst, const void* gsrc) {
    asm volatile("cp.async.cg.shared.global [%0], [%1], 16;" :: "r"(sdst), "l"(gsrc));
}
#define CP_COMMIT() asm volatile("cp.async.commit_group;" ::: "memory")
#define CP_WAIT1()  asm volatile("cp.async.wait_group 1;" ::: "memory")

#define LDSM_X4(r0, r1, r2, r3, addr) \
    asm volatile("ldmatrix.sync.aligned.m8n8.x4.shared.b16 {%0,%1,%2,%3}, [%4];" \
        : "=r"(r0), "=r"(r1), "=r"(r2), "=r"(r3) : "r"(addr))
#define LDSM_X2(r0, r1, addr) \
    asm volatile("ldmatrix.sync.aligned.m8n8.x2.shared.b16 {%0,%1}, [%2];" \
        : "=r"(r0), "=r"(r1) : "r"(addr))

__device__ __forceinline__ void mma_16816(float* c, const uint32_t* a, const uint32_t* b) {
    asm volatile(
        "mma.sync.aligned.m16n8k16.row.col.f32.f16.f16.f32 "
        "{%0,%1,%2,%3}, {%4,%5,%6,%7}, {%8,%9}, {%0,%1,%2,%3};"
        : "+f"(c[0]), "+f"(c[1]), "+f"(c[2]), "+f"(c[3])
        : "r"(a[0]), "r"(a[1]), "r"(a[2]), "r"(a[3]), "r"(b[0]), "r"(b[1]));
}

__device__ __forceinline__ void split2h(float x, __half& h, __half& m) {
    h = __float2half_rn(x);
    m = __float2half_rn(x - __half2float(h));
}

// ===================== fp16 split GEMM via mma.sync =====================
// C[8192, Nout](+epilogue) = escale * sum_terms A_c[8192,K] @ B_c[1024,K]^T
// NTERMS=3: 2 components/operand, terms hh+hm+mh.  NTERMS=1: h-only, 1 term.
// block tile 128x128, BK=32, 8 warps (warp tile 64x32), 2-stage cp.async, 2 CTA/SM.
//  MODE 0: v = escale*acc + bias[n]; store stride D_BOT; also split2 -> oc0/oc1
//  MODE 1: v = escale*acc;           store stride Nout, guard n<Nout
//  MODE 2: v = escale*acc + aux[m*D_BOT+n]; store stride D_BOT
//  MODE 3: v = escale*acc;           store stride Nout, guard
template <int NTERMS, int MODE>
__global__ void __launch_bounds__(256, 2)
gemm_mma(const __half* __restrict__ A, size_t sA,
         const __half* __restrict__ B, size_t sB,
         float* __restrict__ C, int K, int Nout, float escale,
         const float* __restrict__ aux,
         __half* __restrict__ oc0, __half* __restrict__ oc1)
{
    extern __shared__ __align__(128) char smem[];
    const uint32_t sb = smem_u32(smem);
    const int tid = threadIdx.x;
    const int wid = tid >> 5;
    const int lane = tid & 31;
    const int bm = blockIdx.y * 128;
    const int bn = blockIdx.x * 128;

    constexpr int NCL = (NTERMS == 1) ? 1 : 2;   // components loaded per operand
    constexpr int TILEB = 128 * 80;              // 10240 B (64B data + 16B pad per row)
    constexpr int STAGE = 2 * NCL * TILEB;

    const int wm = (wid >> 2) * 64;
    const int wn = (wid & 3) * 32;

    const uint32_t a_lo = (uint32_t)((lane & 15) * 80 + (lane >> 4) * 16);
    const uint32_t b_lo = (uint32_t)((lane & 7) * 80 + ((lane >> 3) & 1) * 16);

    const int l_row0 = tid >> 2;
    const int l_seg = tid & 3;

    float acc[4][4][4];
#pragma unroll
    for (int i = 0; i < 4; i++)
#pragma unroll
        for (int j = 0; j < 4; j++)
#pragma unroll
            for (int q = 0; q < 4; q++) acc[i][j][q] = 0.f;

    const int nch = K >> 5;

    auto load_chunk = [&](int ci) {
        const int s = ci & 1;
        const int k0 = ci << 5;
        const uint32_t st = sb + (uint32_t)s * STAGE;
#pragma unroll
        for (int c = 0; c < 2 * NCL; c++) {
            const __half* base = (c < NCL)
                ? A + (size_t)c * sA + (size_t)bm * K + k0
                : B + (size_t)(c - NCL) * sB + (size_t)bn * K + k0;
#pragma unroll
            for (int j = 0; j < 2; j++) {
                const int row = l_row0 + j * 64;
                cp16(st + (uint32_t)(c * TILEB + row * 80 + l_seg * 16),
                     base + (size_t)row * K + l_seg * 8);
            }
        }
        CP_COMMIT();
    };

    load_chunk(0);
    load_chunk(1);

    for (int i = 0; i < nch; i++) {
        CP_WAIT1();
        __syncthreads();
        const uint32_t st = sb + (uint32_t)(i & 1) * STAGE;
#pragma unroll
        for (int kk = 0; kk < 2; kk++) {
            uint32_t bfr[NCL][4][2];
#pragma unroll
            for (int c = 0; c < NCL; c++)
#pragma unroll
                for (int nt = 0; nt < 4; nt++)
                    LDSM_X2(bfr[c][nt][0], bfr[c][nt][1],
                            st + (uint32_t)((NCL + c) * TILEB) + (uint32_t)(wn * 80) + b_lo
                               + (uint32_t)(nt * 8 * 80 + kk * 32));
#pragma unroll
            for (int ca = 0; ca < NCL; ca++) {
                uint32_t afr[4][4];
#pragma unroll
                for (int mt = 0; mt < 4; mt++)
                    LDSM_X4(afr[mt][0], afr[mt][1], afr[mt][2], afr[mt][3],
                            st + (uint32_t)(ca * TILEB) + (uint32_t)(wm * 80) + a_lo
                               + (uint32_t)(mt * 16 * 80 + kk * 32));
#pragma unroll
                for (int cb = 0; cb < NCL; cb++) {
                    if (NTERMS == 1 || ca + cb < 2) {
#pragma unroll
                        for (int mt = 0; mt < 4; mt++)
#pragma unroll
                            for (int nt = 0; nt < 4; nt++)
                                mma_16816(acc[mt][nt], afr[mt], bfr[cb][nt]);
                    }
                }
            }
        }
        __syncthreads();
        if (i + 2 < nch) load_chunk(i + 2);
    }

    // ---------------- epilogue ----------------
    const int r0 = lane >> 2;
    const int c0 = (lane & 3) * 2;
#pragma unroll
    for (int mt = 0; mt < 4; mt++) {
#pragma unroll
        for (int half = 0; half < 2; half++) {
            const int m = bm + wm + mt * 16 + r0 + half * 8;
#pragma unroll
            for (int nt = 0; nt < 4; nt++) {
                const int n = bn + wn + nt * 8 + c0;
                float v0 = acc[mt][nt][half * 2 + 0] * escale;
                float v1 = acc[mt][nt][half * 2 + 1] * escale;
                if (MODE == 0) {
                    const float2 bs = *reinterpret_cast<const float2*>(aux + n);
                    v0 += bs.x; v1 += bs.y;
                    const size_t o = (size_t)m * D_BOT + n;
                    *reinterpret_cast<float2*>(C + o) = make_float2(v0, v1);
                    __half h0, mm0, h1, mm1;
                    split2h(v0, h0, mm0); split2h(v1, h1, mm1);
                    __half2 ph; ph.x = h0; ph.y = h1;
                    __half2 pm; pm.x = mm0; pm.y = mm1;
                    *reinterpret_cast<__half2*>(oc0 + o) = ph;
                    *reinterpret_cast<__half2*>(oc1 + o) = pm;
                } else if (MODE == 2) {
                    const float2 r = *reinterpret_cast<const float2*>(aux + (size_t)m * D_BOT + n);
                    v0 += r.x; v1 += r.y;
                    *reinterpret_cast<float2*>(C + (size_t)m * D_BOT + n) = make_float2(v0, v1);
                } else {
                    if (n < Nout)
                        *reinterpret_cast<float2*>(C + (size_t)m * Nout + n) = make_float2(v0, v1);
                }
            }
        }
    }
}

// ===================== feature split (float4) =====================
__global__ void __launch_bounds__(256)
split2_feat(const float* __restrict__ src, __half* __restrict__ c0, __half* __restrict__ c1)
{
    const size_t total4 = (size_t)B_ROWS * D_INF / 4;
    for (size_t i = blockIdx.x * (size_t)blockDim.x + threadIdx.x; i < total4;
         i += (size_t)gridDim.x * blockDim.x) {
        float4 v = reinterpret_cast<const float4*>(src)[i];
        const float x[4] = {v.x, v.y, v.z, v.w};
        __half h[4], m[4];
#pragma unroll
        for (int p = 0; p < 4; p++) split2h(x[p], h[p], m[p]);
        __half2 ph0; ph0.x = h[0]; ph0.y = h[1];
        __half2 ph1; ph1.x = h[2]; ph1.y = h[3];
        __half2 pm0; pm0.x = m[0]; pm0.y = m[1];
        __half2 pm1; pm1.x = m[2]; pm1.y = m[3];
        uint2 pk0, pk1;
        pk0.x = *reinterpret_cast<uint32_t*>(&ph0);
        pk0.y = *reinterpret_cast<uint32_t*>(&ph1);
        pk1.x = *reinterpret_cast<uint32_t*>(&pm0);
        pk1.y = *reinterpret_cast<uint32_t*>(&pm1);
        reinterpret_cast<uint2*>(c0)[i] = pk0;
        reinterpret_cast<uint2*>(c1)[i] = pk1;
    }
}

// ===================== fused weight prep (one launch) =====================
// blocks [0, NB_WB)            : W_b split2 (*SW), 1024 rows x 2048
// blocks [NB_WB, +NB_W1)       : W1 split2 (*SW), pad to 1024 rows x 1024
// blocks [.., +NB_W2)          : W2 h-only convert, pad to 1024 rows x 1024
// blocks [.., +NB_CT)          : centroid transpose -> cTh [D_BOT, C_PAD]
#define NB_WB 256
#define NB_W1 128
#define NB_W2 64
#define NB_CT (32 * 32)   // (D_BOT/32) * (C_PAD/32) = 1024 tiles
__global__ void __launch_bounds__(256)
prep_w(const float* __restrict__ W_b, const float* __restrict__ W1,
       const float* __restrict__ W2, const float* __restrict__ centroid,
       __half* __restrict__ wb0, __half* __restrict__ wb1,
       __half* __restrict__ w10, __half* __restrict__ w11,
       __half* __restrict__ w2h)
{
    const int b = blockIdx.x;
    if (b < NB_WB) {
        // W_b split2: 1024x2048, no padding needed
        const size_t total4 = (size_t)D_BOT * D_INF / 4;
        for (size_t i = (size_t)b * blockDim.x + threadIdx.x; i < total4;
             i += (size_t)NB_WB * blockDim.x) {
            float4 v = reinterpret_cast<const float4*>(W_b)[i];
            const float x[4] = {v.x * SW, v.y * SW, v.z * SW, v.w * SW};
            __half h[4], m[4];
#pragma unroll
            for (int p = 0; p < 4; p++) split2h(x[p], h[p], m[p]);
            __half2 ph0; ph0.x = h[0]; ph0.y = h[1];
            __half2 ph1; ph1.x = h[2]; ph1.y = h[3];
            __half2 pm0; pm0.x = m[0]; pm0.y = m[1];
            __half2 pm1; pm1.x = m[2]; pm1.y = m[3];
            uint2 pk0, pk1;
            pk0.x = *reinterpret_cast<uint32_t*>(&ph0);
            pk0.y = *reinterpret_cast<uint32_t*>(&ph1);
            pk1.x = *reinterpret_cast<uint32_t*>(&pm0);
            pk1.y = *reinterpret_cast<uint32_t*>(&pm1);
            reinterpret_cast<uint2*>(wb0)[i] = pk0;
            reinterpret_cast<uint2*>(wb1)[i] = pk1;
        }
    } else if (b < NB_WB + NB_W1) {
        // W1 split2: 1000x1024 padded to 1024 rows
        const int bb = b - NB_WB;
        const size_t total4 = (size_t)C_PAD * D_BOT / 4;
        for (size_t i = (size_t)bb * blockDim.x + threadIdx.x; i < total4;
             i += (size_t)NB_W1 * blockDim.x) {
            const int row = (int)((i * 4) >> 10);
            float4 v = (row < C_CLS) ? reinterpret_cast<const float4*>(W1)[i]
                                     : make_float4(0.f, 0.f, 0.f, 0.f);
            const float x[4] = {v.x * SW, v.y * SW, v.z * SW, v.w * SW};
            __half h[4], m[4];
#pragma unroll
            for (int p = 0; p < 4; p++) split2h(x[p], h[p], m[p]);
            __half2 ph0; ph0.x = h[0]; ph0.y = h[1];
            __half2 ph1; ph1.x = h[2]; ph1.y = h[3];
            __half2 pm0; pm0.x = m[0]; pm0.y = m[1];
            __half2 pm1; pm1.x = m[2]; pm1.y = m[3];
            uint2 pk0, pk1;
            pk0.x = *reinterpret_cast<uint32_t*>(&ph0);
            pk0.y = *reinterpret_cast<uint32_t*>(&ph1);
            pk1.x = *reinterpret_cast<uint32_t*>(&pm0);
            pk1.y = *reinterpret_cast<uint32_t*>(&pm1);
            reinterpret_cast<uint2*>(w10)[i] = pk0;
            reinterpret_cast<uint2*>(w11)[i] = pk1;
        }
    } else if (b < NB_WB + NB_W1 + NB_W2) {
        // W2 h-only: 1000x1024 padded to 1024 rows
        const int bb = b - NB_WB - NB_W1;
        const size_t total4 = (size_t)C_PAD * D_BOT / 4;
        for (size_t i = (size_t)bb * blockDim.x + threadIdx.x; i < total4;
             i += (size_t)NB_W2 * blockDim.x) {
            const int row = (int)((i * 4) >> 10);
            float4 v = (row < C_CLS) ? reinterpret_cast<const float4*>(W2)[i]
                                     : make_float4(0.f, 0.f, 0.f, 0.f);
            __half2 p0; p0.x = __float2half_rn(v.x); p0.y = __float2half_rn(v.y);
            __half2 p1; p1.x = __float2half_rn(v.z); p1.y = __float2half_rn(v.w);
            uint2 pk;
            pk.x = *reinterpret_cast<uint32_t*>(&p0);
            pk.y = *reinterpret_cast<uint32_t*>(&p1);
            reinterpret_cast<uint2*>(w2h)[i] = pk;
        }
    } else {
        // centroid transpose: tile (bx along D_BOT, by along C_PAD)
        __shared__ float tile[32][33];
        const int t = b - NB_WB - NB_W1 - NB_W2;
        const int bx = (t & 31) * 32;           // d (D_BOT/32 = 32)
        const int by = (t >> 5) * 32;           // c (C_PAD/32 = 32)
        const int tx = threadIdx.x & 31;
        const int ty = threadIdx.x >> 5;        // 0..7
        const int x = bx + tx;
#pragma unroll
        for (int i = 0; i < 32; i += 8) {
            const int c = by + ty + i;
            tile[ty + i][tx] = (c < C_CLS) ? centroid[(size_t)c * D_BOT + x] : 0.f;
        }
        __syncthreads();
        const int c2 = by + tx;
#pragma unroll
        for (int i = 0; i < 32; i += 8) {
            const int d2 = bx + ty + i;
            g_cTh[(size_t)d2 * C_PAD + c2] = __float2half_rn(tile[tx][ty + i]);
        }
    }
}

// fused warp-per-row: L2 norm of features_aug row, h-only convert of x = row/||row||
__global__ void __launch_bounds__(256)
norm_h(const float* __restrict__ src, __half* __restrict__ c0)
{
    const int warp = threadIdx.x >> 5;
    const int lane = threadIdx.x & 31;
    const int row = blockIdx.x * 8 + warp;
    const float4* xr = reinterpret_cast<const float4*>(src + (size_t)row * D_BOT);

    float4 vv[8];
    float s = 0.f;
#pragma unroll
    for (int i = 0; i < 8; i++) {
        vv[i] = xr[lane + i * 32];
        s += vv[i].x * vv[i].x + vv[i].y * vv[i].y + vv[i].z * vv[i].z + vv[i].w * vv[i].w;
    }
#pragma unroll
    for (int off = 16; off > 0; off >>= 1)
        s += __shfl_xor_sync(0xFFFFFFFFu, s, off);
    const float inv = 1.f / fmaxf(sqrtf(s), EPSN);

    uint2* outp = reinterpret_cast<uint2*>(c0 + (size_t)row * D_BOT);
#pragma unroll
    for (int i = 0; i < 8; i++) {
        __half2 p0; p0.x = __float2half_rn(vv[i].x * inv); p0.y = __float2half_rn(vv[i].y * inv);
        __half2 p1; p1.x = __float2half_rn(vv[i].z * inv); p1.y = __float2half_rn(vv[i].w * inv);
        uint2 pk;
        pk.x = *reinterpret_cast<uint32_t*>(&p0);
        pk.y = *reinterpret_cast<uint32_t*>(&p1);
        outp[lane + i * 32] = pk;
    }
}

// ============ warp-per-row masked softmax -> sm1 h-only (col-padded, fp16) ==========
__global__ void __launch_bounds__(256)
mask_softmax(const float* __restrict__ logits)
{
    const int warp = threadIdx.x >> 5;
    const int lane = threadIdx.x & 31;
    const int row = blockIdx.x * 8 + warp;
    const float* x = logits + (size_t)row * C_CLS;

    float v[32];
    float lmax = -INFINITY;
    int limax = C_PAD;
#pragma unroll
    for (int i = 0; i < 16; i++) {
        const int j = i * 64 + lane * 2;
        const float a = (j < C_CLS) ? x[j] : -INFINITY;
        const float b = (j + 1 < C_CLS) ? x[j + 1] : -INFINITY;
        v[2 * i] = a; v[2 * i + 1] = b;
        if (a > lmax) { lmax = a; limax = j; }
        if (b > lmax) { lmax = b; limax = j + 1; }
    }
#pragma unroll
    for (int off = 16; off > 0; off >>= 1) {
        const float ov = __shfl_xor_sync(0xFFFFFFFFu, lmax, off);
        const int   oi = __shfl_xor_sync(0xFFFFFFFFu, limax, off);
        if (ov > lmax || (ov == lmax && oi < limax)) { lmax = ov; limax = oi; }
    }
    const int predict = limax;
    const float rowmax = lmax;
    const bool priv = (predict >= SHARE);

    float e[32];
    float lsum = 0.f;
#pragma unroll
    for (int i = 0; i < 32; i++) {
        const int j = (i >> 1) * 64 + lane * 2 + (i & 1);
        float ee = 0.f;
        if (j < C_CLS) {
            bool mask;
            if (j == predict) mask = false;
            else if (priv)    mask = true;
            else              mask = (j < SHARE);
            ee = expf((mask ? NEG_FILL : v[i]) - rowmax);
            lsum += ee;
        }
        e[i] = ee;
    }
#pragma unroll
    for (int off = 16; off > 0; off >>= 1)
        lsum += __shfl_xor_sync(0xFFFFFFFFu, lsum, off);
    const float inv = 1.f / lsum;

    __half* o0 = g_sm1h + (size_t)row * C_PAD;
#pragma unroll
    for (int i = 0; i < 16; i++) {
        const int j = i * 64 + lane * 2;
        __half2 p;
        p.x = __float2half_rn(e[2 * i] * inv);
        p.y = __float2half_rn(e[2 * i + 1] * inv);
        *reinterpret_cast<__half2*>(o0 + j) = p;
    }
}

// ===================== warp-per-row plain softmax =====================
__global__ void __launch_bounds__(256)
softmax_rows(const float* __restrict__ in, float* __restrict__ outp)
{
    const int warp = threadIdx.x >> 5;
    const int lane = threadIdx.x & 31;
    const int row = blockIdx.x * 8 + warp;
    const float* x = in + (size_t)row * C_CLS;

    float v[32];
    float lmax = -INFINITY;
#pragma unroll
    for (int i = 0; i < 16; i++) {
        const int j = i * 64 + lane * 2;
        v[2 * i]     = (j < C_CLS) ? x[j] : -INFINITY;
        v[2 * i + 1] = (j + 1 < C_CLS) ? x[j + 1] : -INFINITY;
        lmax = fmaxf(lmax, fmaxf(v[2 * i], v[2 * i + 1]));
    }
#pragma unroll
    for (int off = 16; off > 0; off >>= 1)
        lmax = fmaxf(lmax, __shfl_xor_sync(0xFFFFFFFFu, lmax, off));

    float e[32];
    float lsum = 0.f;
#pragma unroll
    for (int i = 0; i < 32; i++) {
        const int j = (i >> 1) * 64 + lane * 2 + (i & 1);
        float ee = 0.f;
        if (j < C_CLS) { ee = expf(v[i] - lmax); lsum += ee; }
        e[i] = ee;
    }
#pragma unroll
    for (int off = 16; off > 0; off >>= 1)
        lsum += __shfl_xor_sync(0xFFFFFFFFu, lsum, off);
    const float inv = 1.f / lsum;

    float* o = outp + (size_t)row * C_CLS;
#pragma unroll
    for (int i = 0; i < 16; i++) {
        const int j = i * 64 + lane * 2;
        if (j + 1 < C_CLS) {
            *reinterpret_cast<float2*>(o + j) = make_float2(e[2 * i] * inv, e[2 * i + 1] * inv);
        } else if (j < C_CLS) {
            o[j] = e[2 * i] * inv;
        }
    }
}

// =====================================================================
extern "C" void kernel_launch(void* const* d_in, const int* in_sizes, int n_in,
                              void* d_out, int out_size)
{
    const float* features = (const float*)d_in[0];
    const float* W_b      = (const float*)d_in[1];
    const float* b_b      = (const float*)d_in[2];
    const float* W1       = (const float*)d_in[3];
    const float* W2       = (const float*)d_in[4];
    const float* centroid = (const float*)d_in[5];

    float* out = (float*)d_out;
    float* feats        = out;
    float* features_aug = feats + (size_t)B_ROWS * D_BOT;
    float* outputs1     = features_aug + (size_t)B_ROWS * D_BOT;
    float* outputs2     = outputs1 + (size_t)B_ROWS * C_CLS;
    float* softmax_out  = outputs2 + (size_t)B_ROWS * C_CLS;

    __half *feat2, *Wb2, *feats2, *W1s, *sm1h, *cTh, *faugh, *W2h;
    cudaGetSymbolAddress((void**)&feat2,  g_feat2);
    cudaGetSymbolAddress((void**)&Wb2,    g_Wb2);
    cudaGetSymbolAddress((void**)&feats2, g_feats2);
    cudaGetSymbolAddress((void**)&W1s,    g_W1s);
    cudaGetSymbolAddress((void**)&sm1h,   g_sm1h);
    cudaGetSymbolAddress((void**)&cTh,    g_cTh);
    cudaGetSymbolAddress((void**)&faugh,  g_faugh);
    cudaGetSymbolAddress((void**)&W2h,    g_W2h);

    const size_t S_feat  = (size_t)B_ROWS * D_INF;
    const size_t S_Wb    = (size_t)D_BOT  * D_INF;
    const size_t S_feats = (size_t)B_ROWS * D_BOT;
    const size_t S_W1    = (size_t)C_PAD  * D_BOT;

    constexpr int TILEB = 128 * 80;
    constexpr int SMEMG  = 2 * 4 * TILEB;   // 81920 — NTERMS=3 path, 2 CTAs/SM
    constexpr int SMEMG1 = 2 * 2 * TILEB;   // 40960 — NTERMS=1 path
    cudaFuncSetAttribute(gemm_mma<3, 0>, cudaFuncAttributeMaxDynamicSharedMemorySize, SMEMG);
    cudaFuncSetAttribute(gemm_mma<3, 1>, cudaFuncAttributeMaxDynamicSharedMemorySize, SMEMG);
    cudaFuncSetAttribute(gemm_mma<1, 2>, cudaFuncAttributeMaxDynamicSharedMemorySize, SMEMG1);
    cudaFuncSetAttribute(gemm_mma<1, 3>, cudaFuncAttributeMaxDynamicSharedMemorySize, SMEMG1);

    const dim3 blk(256);
    const dim3 grid8(8, 64);
    const float invSW = 1.0f / SW;

    // feature split (float4) + ALL weight prep in one launch
    split2_feat<<<2048, blk>>>(features, feat2, feat2 + S_feat);
    prep_w<<<NB_WB + NB_W1 + NB_W2 + NB_CT, blk>>>(W_b, W1, W2, centroid,
                                                   Wb2, Wb2 + S_Wb,
                                                   W1s, W1s + S_W1, W2h);

    // GEMM1: feats = features @ W_b^T + b_b (3-term fp16 split; epilogue emits feats2)
    gemm_mma<3, 0><<<grid8, blk, SMEMG>>>(feat2, S_feat, Wb2, S_Wb, feats, D_INF, D_BOT,
                                          invSW, b_b, feats2, feats2 + S_feats);

    // GEMM2: outputs1 = feats @ W1^T (3-term — argmax-critical, do not cut)
    gemm_mma<3, 1><<<grid8, blk, SMEMG>>>(feats2, S_feats, W1s, S_W1, outputs1, D_BOT, C_CLS,
                                          invSW, nullptr, nullptr, nullptr);

    // masked softmax (warp-per-row, h-only sm1)
    mask_softmax<<<B_ROWS / 8, blk>>>(outputs1);

    // GEMM3: features_aug = sm1 @ centroid + feats  (1-term h*h; feat_oa ~2% of feats)
    gemm_mma<1, 2><<<grid8, blk, SMEMG1>>>(sm1h, 0, cTh, 0, features_aug, C_PAD, D_BOT,
                                           1.0f, feats, nullptr, nullptr);

    // fused warp-per-row normalize + h-only convert
    norm_h<<<B_ROWS / 8, blk>>>(features_aug, faugh);

    // GEMM4: outputs2 = x @ W2^T / TEMP  (1-term h*h: x unit-norm, err ~2e-4 rel << 1e-3)
    gemm_mma<1, 3><<<grid8, blk, SMEMG1>>>(faugh, 0, W2h, 0, outputs2, D_BOT, C_CLS,
                                           20.0f, nullptr, nullptr, nullptr);

    softmax_rows<<<B_ROWS / 8, blk>>>(outputs2, softmax_out);
}

// round 14
// speedup vs baseline: 1.4866x; 1.0022x over previous
#include <cuda_runtime.h>
#include <cuda_fp16.h>
#include <math.h>
#include <stdint.h>

#define B_ROWS   8192
#define D_INF    2048
#define D_BOT    1024
#define C_CLS    1000
#define C_PAD    1024
#define SHARE    500
#define NEG_FILL (-1e9f)
#define EPSN     1e-12f
#define SW       512.0f           // weight pre-scale (keeps fp16 m-components normal)

// ===================== scratch (static device globals) =====================
__device__ __align__(1024) __half g_feat2 [2][(size_t)B_ROWS * D_INF];
__device__ __align__(1024) __half g_Wb2   [2][(size_t)D_BOT  * D_INF];
__device__ __align__(1024) __half g_feats2[2][(size_t)B_ROWS * D_BOT];
__device__ __align__(1024) __half g_W1s   [2][(size_t)C_PAD  * D_BOT];
__device__ __align__(1024) __half g_sm1h  [(size_t)B_ROWS * C_PAD];   // sm1 h-only
__device__ __align__(1024) __half g_cTh   [(size_t)D_BOT  * C_PAD];   // centroid^T h-only
__device__ __align__(1024) __half g_faugh [(size_t)B_ROWS * D_BOT];   // normalized x, h-only
__device__ __align__(1024) __half g_W2h   [(size_t)C_PAD  * D_BOT];   // W2 h-only

// ===================== helpers =====================
__device__ __forceinline__ uint32_t smem_u32(const void* p) {
    return (uint32_t)__cvta_generic_to_shared(p);
}
__device__ __forceinline__ void cp16(uint32_t sdst, const void* gsrc) {
    asm volatile("cp.async.cg.shared.global [%0], [%1], 16;" :: "r"(sdst), "l"(gsrc));
}
#define CP_COMMIT() asm volatile("cp.async.commit_group;" ::: "memory")
#define CP_WAIT1()  asm volatile("cp.async.wait_group 1;" ::: "memory")

#define LDSM_X4(r0, r1, r2, r3, addr) \
    asm volatile("ldmatrix.sync.aligned.m8n8.x4.shared.b16 {%0,%1,%2,%3}, [%4];" \
        : "=r"(r0), "=r"(r1), "=r"(r2), "=r"(r3) : "r"(addr))

__device__ __forceinline__ void mma_16816(float* c, const uint32_t* a, const uint32_t* b) {
    asm volatile(
        "mma.sync.aligned.m16n8k16.row.col.f32.f16.f16.f32 "
        "{%0,%1,%2,%3}, {%4,%5,%6,%7}, {%8,%9}, {%0,%1,%2,%3};"
        : "+f"(c[0]), "+f"(c[1]), "+f"(c[2]), "+f"(c[3])
        : "r"(a[0]), "r"(a[1]), "r"(a[2]), "r"(a[3]), "r"(b[0]), "r"(b[1]));
}

__device__ __forceinline__ void split2h(float x, __half& h, __half& m) {
    h = __float2half_rn(x);
    m = __float2half_rn(x - __half2float(h));
}

// ===================== fp16 split GEMM via mma.sync =====================
// C[8192, Nout](+epilogue) = escale * sum_terms A_c[8192,K] @ B_c[1024,K]^T
// NTERMS=3: 2 components/operand, terms hh+hm+mh.  NTERMS=1: h-only, 1 term.
// block tile 128x128, BK=32, 8 warps (warp tile 64x32), 2-stage cp.async, 2 CTA/SM.
// Per kk step: ALL fragments (A both comps, B both comps via ldsm.x4) hoisted
// before the uninterrupted MMA stream — hides LDSM latency under 16+ MMAs.
//  MODE 0: v = escale*acc + bias[n]; store stride D_BOT; also split2 -> oc0/oc1
//  MODE 1: v = escale*acc;           store stride Nout, guard n<Nout
//  MODE 2: v = escale*acc + aux[m*D_BOT+n]; store stride D_BOT
//  MODE 3: v = escale*acc;           store stride Nout, guard
template <int NTERMS, int MODE>
__global__ void __launch_bounds__(256, 2)
gemm_mma(const __half* __restrict__ A, size_t sA,
         const __half* __restrict__ B, size_t sB,
         float* __restrict__ C, int K, int Nout, float escale,
         const float* __restrict__ aux,
         __half* __restrict__ oc0, __half* __restrict__ oc1)
{
    extern __shared__ __align__(128) char smem[];
    const uint32_t sb = smem_u32(smem);
    const int tid = threadIdx.x;
    const int wid = tid >> 5;
    const int lane = tid & 31;
    const int bm = blockIdx.y * 128;
    const int bn = blockIdx.x * 128;

    constexpr int NCL = (NTERMS == 1) ? 1 : 2;   // components loaded per operand
    constexpr int TILEB = 128 * 80;              // 10240 B (64B data + 16B pad per row)
    constexpr int STAGE = 2 * NCL * TILEB;

    const int wm = (wid >> 2) * 64;
    const int wn = (wid & 3) * 32;

    // A x4: 16 rows (lane&15), 16B half by lane>>4
    const uint32_t a_lo = (uint32_t)((lane & 15) * 80 + (lane >> 4) * 16);
    // B x4: row-octet pair — rows (lane&7) + ((lane>>4)&1)*8, 16B half by bit3
    const uint32_t b4_lo = (uint32_t)(((lane & 7) + ((lane >> 4) & 1) * 8) * 80
                                      + ((lane >> 3) & 1) * 16);

    const int l_row0 = tid >> 2;
    const int l_seg = tid & 3;

    float acc[4][4][4];
#pragma unroll
    for (int i = 0; i < 4; i++)
#pragma unroll
        for (int j = 0; j < 4; j++)
#pragma unroll
            for (int q = 0; q < 4; q++) acc[i][j][q] = 0.f;

    const int nch = K >> 5;

    auto load_chunk = [&](int ci) {
        const int s = ci & 1;
        const int k0 = ci << 5;
        const uint32_t st = sb + (uint32_t)s * STAGE;
#pragma unroll
        for (int c = 0; c < 2 * NCL; c++) {
            const __half* base = (c < NCL)
                ? A + (size_t)c * sA + (size_t)bm * K + k0
                : B + (size_t)(c - NCL) * sB + (size_t)bn * K + k0;
#pragma unroll
            for (int j = 0; j < 2; j++) {
                const int row = l_row0 + j * 64;
                cp16(st + (uint32_t)(c * TILEB + row * 80 + l_seg * 16),
                     base + (size_t)row * K + l_seg * 8);
            }
        }
        CP_COMMIT();
    };

    load_chunk(0);
    load_chunk(1);

    for (int i = 0; i < nch; i++) {
        CP_WAIT1();
        __syncthreads();
        const uint32_t st = sb + (uint32_t)(i & 1) * STAGE;
#pragma unroll
        for (int kk = 0; kk < 2; kk++) {
            // ---- hoist ALL fragments for this kk ----
            uint32_t bfr[NCL][4][2];
#pragma unroll
            for (int c = 0; c < NCL; c++)
#pragma unroll
                for (int np = 0; np < 2; np++)
                    LDSM_X4(bfr[c][np * 2][0], bfr[c][np * 2][1],
                            bfr[c][np * 2 + 1][0], bfr[c][np * 2 + 1][1],
                            st + (uint32_t)((NCL + c) * TILEB)
                               + (uint32_t)((wn + np * 16) * 80) + b4_lo
                               + (uint32_t)(kk * 32));
            uint32_t afr[NCL][4][4];
#pragma unroll
            for (int c = 0; c < NCL; c++)
#pragma unroll
                for (int mt = 0; mt < 4; mt++)
                    LDSM_X4(afr[c][mt][0], afr[c][mt][1], afr[c][mt][2], afr[c][mt][3],
                            st + (uint32_t)(c * TILEB) + (uint32_t)(wm * 80) + a_lo
                               + (uint32_t)(mt * 16 * 80 + kk * 32));
            // ---- uninterrupted MMA stream (same term order as before) ----
#pragma unroll
            for (int ca = 0; ca < NCL; ca++)
#pragma unroll
                for (int cb = 0; cb < NCL; cb++) {
                    if (NTERMS == 1 || ca + cb < 2) {
#pragma unroll
                        for (int mt = 0; mt < 4; mt++)
#pragma unroll
                            for (int nt = 0; nt < 4; nt++)
                                mma_16816(acc[mt][nt], afr[ca][mt], bfr[cb][nt]);
                    }
                }
        }
        __syncthreads();
        if (i + 2 < nch) load_chunk(i + 2);
    }

    // ---------------- epilogue ----------------
    const int r0 = lane >> 2;
    const int c0 = (lane & 3) * 2;
#pragma unroll
    for (int mt = 0; mt < 4; mt++) {
#pragma unroll
        for (int half = 0; half < 2; half++) {
            const int m = bm + wm + mt * 16 + r0 + half * 8;
#pragma unroll
            for (int nt = 0; nt < 4; nt++) {
                const int n = bn + wn + nt * 8 + c0;
                float v0 = acc[mt][nt][half * 2 + 0] * escale;
                float v1 = acc[mt][nt][half * 2 + 1] * escale;
                if (MODE == 0) {
                    const float2 bs = *reinterpret_cast<const float2*>(aux + n);
                    v0 += bs.x; v1 += bs.y;
                    const size_t o = (size_t)m * D_BOT + n;
                    *reinterpret_cast<float2*>(C + o) = make_float2(v0, v1);
                    __half h0, mm0, h1, mm1;
                    split2h(v0, h0, mm0); split2h(v1, h1, mm1);
                    __half2 ph; ph.x = h0; ph.y = h1;
                    __half2 pm; pm.x = mm0; pm.y = mm1;
                    *reinterpret_cast<__half2*>(oc0 + o) = ph;
                    *reinterpret_cast<__half2*>(oc1 + o) = pm;
                } else if (MODE == 2) {
                    const float2 r = *reinterpret_cast<const float2*>(aux + (size_t)m * D_BOT + n);
                    v0 += r.x; v1 += r.y;
                    *reinterpret_cast<float2*>(C + (size_t)m * D_BOT + n) = make_float2(v0, v1);
                } else {
                    if (n < Nout)
                        *reinterpret_cast<float2*>(C + (size_t)m * Nout + n) = make_float2(v0, v1);
                }
            }
        }
    }
}

// ===================== feature split (float4) =====================
__global__ void __launch_bounds__(256)
split2_feat(const float* __restrict__ src, __half* __restrict__ c0, __half* __restrict__ c1)
{
    const size_t total4 = (size_t)B_ROWS * D_INF / 4;
    for (size_t i = blockIdx.x * (size_t)blockDim.x + threadIdx.x; i < total4;
         i += (size_t)gridDim.x * blockDim.x) {
        float4 v = reinterpret_cast<const float4*>(src)[i];
        const float x[4] = {v.x, v.y, v.z, v.w};
        __half h[4], m[4];
#pragma unroll
        for (int p = 0; p < 4; p++) split2h(x[p], h[p], m[p]);
        __half2 ph0; ph0.x = h[0]; ph0.y = h[1];
        __half2 ph1; ph1.x = h[2]; ph1.y = h[3];
        __half2 pm0; pm0.x = m[0]; pm0.y = m[1];
        __half2 pm1; pm1.x = m[2]; pm1.y = m[3];
        uint2 pk0, pk1;
        pk0.x = *reinterpret_cast<uint32_t*>(&ph0);
        pk0.y = *reinterpret_cast<uint32_t*>(&ph1);
        pk1.x = *reinterpret_cast<uint32_t*>(&pm0);
        pk1.y = *reinterpret_cast<uint32_t*>(&pm1);
        reinterpret_cast<uint2*>(c0)[i] = pk0;
        reinterpret_cast<uint2*>(c1)[i] = pk1;
    }
}

// ===================== fused weight prep (one launch) =====================
#define NB_WB 256
#define NB_W1 128
#define NB_W2 64
#define NB_CT (32 * 32)
__global__ void __launch_bounds__(256)
prep_w(const float* __restrict__ W_b, const float* __restrict__ W1,
       const float* __restrict__ W2, const float* __restrict__ centroid,
       __half* __restrict__ wb0, __half* __restrict__ wb1,
       __half* __restrict__ w10, __half* __restrict__ w11,
       __half* __restrict__ w2h)
{
    const int b = blockIdx.x;
    if (b < NB_WB) {
        const size_t total4 = (size_t)D_BOT * D_INF / 4;
        for (size_t i = (size_t)b * blockDim.x + threadIdx.x; i < total4;
             i += (size_t)NB_WB * blockDim.x) {
            float4 v = reinterpret_cast<const float4*>(W_b)[i];
            const float x[4] = {v.x * SW, v.y * SW, v.z * SW, v.w * SW};
            __half h[4], m[4];
#pragma unroll
            for (int p = 0; p < 4; p++) split2h(x[p], h[p], m[p]);
            __half2 ph0; ph0.x = h[0]; ph0.y = h[1];
            __half2 ph1; ph1.x = h[2]; ph1.y = h[3];
            __half2 pm0; pm0.x = m[0]; pm0.y = m[1];
            __half2 pm1; pm1.x = m[2]; pm1.y = m[3];
            uint2 pk0, pk1;
            pk0.x = *reinterpret_cast<uint32_t*>(&ph0);
            pk0.y = *reinterpret_cast<uint32_t*>(&ph1);
            pk1.x = *reinterpret_cast<uint32_t*>(&pm0);
            pk1.y = *reinterpret_cast<uint32_t*>(&pm1);
            reinterpret_cast<uint2*>(wb0)[i] = pk0;
            reinterpret_cast<uint2*>(wb1)[i] = pk1;
        }
    } else if (b < NB_WB + NB_W1) {
        const int bb = b - NB_WB;
        const size_t total4 = (size_t)C_PAD * D_BOT / 4;
        for (size_t i = (size_t)bb * blockDim.x + threadIdx.x; i < total4;
             i += (size_t)NB_W1 * blockDim.x) {
            const int row = (int)((i * 4) >> 10);
            float4 v = (row < C_CLS) ? reinterpret_cast<const float4*>(W1)[i]
                                     : make_float4(0.f, 0.f, 0.f, 0.f);
            const float x[4] = {v.x * SW, v.y * SW, v.z * SW, v.w * SW};
            __half h[4], m[4];
#pragma unroll
            for (int p = 0; p < 4; p++) split2h(x[p], h[p], m[p]);
            __half2 ph0; ph0.x = h[0]; ph0.y = h[1];
            __half2 ph1; ph1.x = h[2]; ph1.y = h[3];
            __half2 pm0; pm0.x = m[0]; pm0.y = m[1];
            __half2 pm1; pm1.x = m[2]; pm1.y = m[3];
            uint2 pk0, pk1;
            pk0.x = *reinterpret_cast<uint32_t*>(&ph0);
            pk0.y = *reinterpret_cast<uint32_t*>(&ph1);
            pk1.x = *reinterpret_cast<uint32_t*>(&pm0);
            pk1.y = *reinterpret_cast<uint32_t*>(&pm1);
            reinterpret_cast<uint2*>(w10)[i] = pk0;
            reinterpret_cast<uint2*>(w11)[i] = pk1;
        }
    } else if (b < NB_WB + NB_W1 + NB_W2) {
        const int bb = b - NB_WB - NB_W1;
        const size_t total4 = (size_t)C_PAD * D_BOT / 4;
        for (size_t i = (size_t)bb * blockDim.x + threadIdx.x; i < total4;
             i += (size_t)NB_W2 * blockDim.x) {
            const int row = (int)((i * 4) >> 10);
            float4 v = (row < C_CLS) ? reinterpret_cast<const float4*>(W2)[i]
                                     : make_float4(0.f, 0.f, 0.f, 0.f);
            __half2 p0; p0.x = __float2half_rn(v.x); p0.y = __float2half_rn(v.y);
            __half2 p1; p1.x = __float2half_rn(v.z); p1.y = __float2half_rn(v.w);
            uint2 pk;
            pk.x = *reinterpret_cast<uint32_t*>(&p0);
            pk.y = *reinterpret_cast<uint32_t*>(&p1);
            reinterpret_cast<uint2*>(w2h)[i] = pk;
        }
    } else {
        __shared__ float tile[32][33];
        const int t = b - NB_WB - NB_W1 - NB_W2;
        const int bx = (t & 31) * 32;
        const int by = (t >> 5) * 32;
        const int tx = threadIdx.x & 31;
        const int ty = threadIdx.x >> 5;
        const int x = bx + tx;
#pragma unroll
        for (int i = 0; i < 32; i += 8) {
            const int c = by + ty + i;
            tile[ty + i][tx] = (c < C_CLS) ? centroid[(size_t)c * D_BOT + x] : 0.f;
        }
        __syncthreads();
        const int c2 = by + tx;
#pragma unroll
        for (int i = 0; i < 32; i += 8) {
            const int d2 = bx + ty + i;
            g_cTh[(size_t)d2 * C_PAD + c2] = __float2half_rn(tile[tx][ty + i]);
        }
    }
}

// fused warp-per-row: L2 norm of features_aug row, h-only convert of x = row/||row||
__global__ void __launch_bounds__(256)
norm_h(const float* __restrict__ src, __half* __restrict__ c0)
{
    const int warp = threadIdx.x >> 5;
    const int lane = threadIdx.x & 31;
    const int row = blockIdx.x * 8 + warp;
    const float4* xr = reinterpret_cast<const float4*>(src + (size_t)row * D_BOT);

    float4 vv[8];
    float s = 0.f;
#pragma unroll
    for (int i = 0; i < 8; i++) {
        vv[i] = xr[lane + i * 32];
        s += vv[i].x * vv[i].x + vv[i].y * vv[i].y + vv[i].z * vv[i].z + vv[i].w * vv[i].w;
    }
#pragma unroll
    for (int off = 16; off > 0; off >>= 1)
        s += __shfl_xor_sync(0xFFFFFFFFu, s, off);
    const float inv = 1.f / fmaxf(sqrtf(s), EPSN);

    uint2* outp = reinterpret_cast<uint2*>(c0 + (size_t)row * D_BOT);
#pragma unroll
    for (int i = 0; i < 8; i++) {
        __half2 p0; p0.x = __float2half_rn(vv[i].x * inv); p0.y = __float2half_rn(vv[i].y * inv);
        __half2 p1; p1.x = __float2half_rn(vv[i].z * inv); p1.y = __float2half_rn(vv[i].w * inv);
        uint2 pk;
        pk.x = *reinterpret_cast<uint32_t*>(&p0);
        pk.y = *reinterpret_cast<uint32_t*>(&p1);
        outp[lane + i * 32] = pk;
    }
}

// ============ warp-per-row masked softmax -> sm1 h-only (col-padded, fp16) ==========
__global__ void __launch_bounds__(256)
mask_softmax(const float* __restrict__ logits)
{
    const int warp = threadIdx.x >> 5;
    const int lane = threadIdx.x & 31;
    const int row = blockIdx.x * 8 + warp;
    const float* x = logits + (size_t)row * C_CLS;

    float v[32];
    float lmax = -INFINITY;
    int limax = C_PAD;
#pragma unroll
    for (int i = 0; i < 16; i++) {
        const int j = i * 64 + lane * 2;
        const float a = (j < C_CLS) ? x[j] : -INFINITY;
        const float b = (j + 1 < C_CLS) ? x[j + 1] : -INFINITY;
        v[2 * i] = a; v[2 * i + 1] = b;
        if (a > lmax) { lmax = a; limax = j; }
        if (b > lmax) { lmax = b; limax = j + 1; }
    }
#pragma unroll
    for (int off = 16; off > 0; off >>= 1) {
        const float ov = __shfl_xor_sync(0xFFFFFFFFu, lmax, off);
        const int   oi = __shfl_xor_sync(0xFFFFFFFFu, limax, off);
        if (ov > lmax || (ov == lmax && oi < limax)) { lmax = ov; limax = oi; }
    }
    const int predict = limax;
    const float rowmax = lmax;
    const bool priv = (predict >= SHARE);

    float e[32];
    float lsum = 0.f;
#pragma unroll
    for (int i = 0; i < 32; i++) {
        const int j = (i >> 1) * 64 + lane * 2 + (i & 1);
        float ee = 0.f;
        if (j < C_CLS) {
            bool mask;
            if (j == predict) mask = false;
            else if (priv)    mask = true;
            else              mask = (j < SHARE);
            ee = expf((mask ? NEG_FILL : v[i]) - rowmax);
            lsum += ee;
        }
        e[i] = ee;
    }
#pragma unroll
    for (int off = 16; off > 0; off >>= 1)
        lsum += __shfl_xor_sync(0xFFFFFFFFu, lsum, off);
    const float inv = 1.f / lsum;

    __half* o0 = g_sm1h + (size_t)row * C_PAD;
#pragma unroll
    for (int i = 0; i < 16; i++) {
        const int j = i * 64 + lane * 2;
        __half2 p;
        p.x = __float2half_rn(e[2 * i] * inv);
        p.y = __float2half_rn(e[2 * i + 1] * inv);
        *reinterpret_cast<__half2*>(o0 + j) = p;
    }
}

// ===================== warp-per-row plain softmax =====================
__global__ void __launch_bounds__(256)
softmax_rows(const float* __restrict__ in, float* __restrict__ outp)
{
    const int warp = threadIdx.x >> 5;
    const int lane = threadIdx.x & 31;
    const int row = blockIdx.x * 8 + warp;
    const float* x = in + (size_t)row * C_CLS;

    float v[32];
    float lmax = -INFINITY;
#pragma unroll
    for (int i = 0; i < 16; i++) {
        const int j = i * 64 + lane * 2;
        v[2 * i]     = (j < C_CLS) ? x[j] : -INFINITY;
        v[2 * i + 1] = (j + 1 < C_CLS) ? x[j + 1] : -INFINITY;
        lmax = fmaxf(lmax, fmaxf(v[2 * i], v[2 * i + 1]));
    }
#pragma unroll
    for (int off = 16; off > 0; off >>= 1)
        lmax = fmaxf(lmax, __shfl_xor_sync(0xFFFFFFFFu, lmax, off));

    float e[32];
    float lsum = 0.f;
#pragma unroll
    for (int i = 0; i < 32; i++) {
        const int j = (i >> 1) * 64 + lane * 2 + (i & 1);
        float ee = 0.f;
        if (j < C_CLS) { ee = expf(v[i] - lmax); lsum += ee; }
        e[i] = ee;
    }
#pragma unroll
    for (int off = 16; off > 0; off >>= 1)
        lsum += __shfl_xor_sync(0xFFFFFFFFu, lsum, off);
    const float inv = 1.f / lsum;

    float* o = outp + (size_t)row * C_CLS;
#pragma unroll
    for (int i = 0; i < 16; i++) {
        const int j = i * 64 + lane * 2;
        if (j + 1 < C_CLS) {
            *reinterpret_cast<float2*>(o + j) = make_float2(e[2 * i] * inv, e[2 * i + 1] * inv);
        } else if (j < C_CLS) {
            o[j] = e[2 * i] * inv;
        }
    }
}

// =====================================================================
extern "C" void kernel_launch(void* const* d_in, const int* in_sizes, int n_in,
                              void* d_out, int out_size)
{
    const float* features = (const float*)d_in[0];
    const float* W_b      = (const float*)d_in[1];
    const float* b_b      = (const float*)d_in[2];
    const float* W1       = (const float*)d_in[3];
    const float* W2       = (const float*)d_in[4];
    const float* centroid = (const float*)d_in[5];

    float* out = (float*)d_out;
    float* feats        = out;
    float* features_aug = feats + (size_t)B_ROWS * D_BOT;
    float* outputs1     = features_aug + (size_t)B_ROWS * D_BOT;
    float* outputs2     = outputs1 + (size_t)B_ROWS * C_CLS;
    float* softmax_out  = outputs2 + (size_t)B_ROWS * C_CLS;

    __half *feat2, *Wb2, *feats2, *W1s, *sm1h, *cTh, *faugh, *W2h;
    cudaGetSymbolAddress((void**)&feat2,  g_feat2);
    cudaGetSymbolAddress((void**)&Wb2,    g_Wb2);
    cudaGetSymbolAddress((void**)&feats2, g_feats2);
    cudaGetSymbolAddress((void**)&W1s,    g_W1s);
    cudaGetSymbolAddress((void**)&sm1h,   g_sm1h);
    cudaGetSymbolAddress((void**)&cTh,    g_cTh);
    cudaGetSymbolAddress((void**)&faugh,  g_faugh);
    cudaGetSymbolAddress((void**)&W2h,    g_W2h);

    const size_t S_feat  = (size_t)B_ROWS * D_INF;
    const size_t S_Wb    = (size_t)D_BOT  * D_INF;
    const size_t S_feats = (size_t)B_ROWS * D_BOT;
    const size_t S_W1    = (size_t)C_PAD  * D_BOT;

    constexpr int TILEB = 128 * 80;
    constexpr int SMEMG  = 2 * 4 * TILEB;   // 81920 — NTERMS=3 path, 2 CTAs/SM
    constexpr int SMEMG1 = 2 * 2 * TILEB;   // 40960 — NTERMS=1 path
    cudaFuncSetAttribute(gemm_mma<3, 0>, cudaFuncAttributeMaxDynamicSharedMemorySize, SMEMG);
    cudaFuncSetAttribute(gemm_mma<3, 1>, cudaFuncAttributeMaxDynamicSharedMemorySize, SMEMG);
    cudaFuncSetAttribute(gemm_mma<1, 2>, cudaFuncAttributeMaxDynamicSharedMemorySize, SMEMG1);
    cudaFuncSetAttribute(gemm_mma<1, 3>, cudaFuncAttributeMaxDynamicSharedMemorySize, SMEMG1);

    const dim3 blk(256);
    const dim3 grid8(8, 64);
    const float invSW = 1.0f / SW;

    // feature split (float4) + ALL weight prep in one launch
    split2_feat<<<2048, blk>>>(features, feat2, feat2 + S_feat);
    prep_w<<<NB_WB + NB_W1 + NB_W2 + NB_CT, blk>>>(W_b, W1, W2, centroid,
                                                   Wb2, Wb2 + S_Wb,
                                                   W1s, W1s + S_W1, W2h);

    // GEMM1: feats = features @ W_b^T + b_b (3-term fp16 split; epilogue emits feats2)
    gemm_mma<3, 0><<<grid8, blk, SMEMG>>>(feat2, S_feat, Wb2, S_Wb, feats, D_INF, D_BOT,
                                          invSW, b_b, feats2, feats2 + S_feats);

    // GEMM2: outputs1 = feats @ W1^T (3-term — argmax-critical, do not cut)
    gemm_mma<3, 1><<<grid8, blk, SMEMG>>>(feats2, S_feats, W1s, S_W1, outputs1, D_BOT, C_CLS,
                                          invSW, nullptr, nullptr, nullptr);

    // masked softmax (warp-per-row, h-only sm1)
    mask_softmax<<<B_ROWS / 8, blk>>>(outputs1);

    // GEMM3: features_aug = sm1 @ centroid + feats  (1-term h*h; feat_oa ~2% of feats)
    gemm_mma<1, 2><<<grid8, blk, SMEMG1>>>(sm1h, 0, cTh, 0, features_aug, C_PAD, D_BOT,
                                           1.0f, feats, nullptr, nullptr);

    // fused warp-per-row normalize + h-only convert
    norm_h<<<B_ROWS / 8, blk>>>(features_aug, faugh);

    // GEMM4: outputs2 = x @ W2^T / TEMP  (1-term h*h: x unit-norm, err ~2e-4 rel << 1e-3)
    gemm_mma<1, 3><<<grid8, blk, SMEMG1>>>(faugh, 0, W2h, 0, outputs2, D_BOT, C_CLS,
                                           20.0f, nullptr, nullptr, nullptr);

    softmax_rows<<<B_ROWS / 8, blk>>>(outputs2, softmax_out);
}

// round 15
// speedup vs baseline: 1.5197x; 1.0223x over previous
#include <cuda_runtime.h>
#include <cuda_fp16.h>
#include <math.h>
#include <stdint.h>

#define B_ROWS   8192
#define D_INF    2048
#define D_BOT    1024
#define C_CLS    1000
#define C_PAD    1024
#define SHARE    500
#define NEG_FILL (-1e9f)
#define EPSN     1e-12f
#define SW       512.0f           // weight pre-scale (keeps fp16 m-components normal)

// ===================== scratch (static device globals) =====================
__device__ __align__(1024) __half g_feat2 [2][(size_t)B_ROWS * D_INF];
__device__ __align__(1024) __half g_Wb2   [2][(size_t)D_BOT  * D_INF];
__device__ __align__(1024) __half g_feats2[2][(size_t)B_ROWS * D_BOT];
__device__ __align__(1024) __half g_W1s   [2][(size_t)C_PAD  * D_BOT];
__device__ __align__(1024) __half g_sm1h  [(size_t)B_ROWS * C_PAD];   // sm1 h-only
__device__ __align__(1024) __half g_cTh   [(size_t)D_BOT  * C_PAD];   // centroid^T h-only
__device__ __align__(1024) __half g_faugh [(size_t)B_ROWS * D_BOT];   // normalized x, h-only
__device__ __align__(1024) __half g_W2h   [(size_t)C_PAD  * D_BOT];   // W2 h-only

// ===================== helpers =====================
__device__ __forceinline__ uint32_t smem_u32(const void* p) {
    return (uint32_t)__cvta_generic_to_shared(p);
}
__device__ __forceinline__ void cp16(uint32_t sdst, const void* gsrc) {
    asm volatile("cp.async.cg.shared.global [%0], [%1], 16;" :: "r"(sdst), "l"(gsrc));
}
#define CP_COMMIT() asm volatile("cp.async.commit_group;" ::: "memory")
#define CP_WAIT1()  asm volatile("cp.async.wait_group 1;" ::: "memory")

#define LDSM_X4(r0, r1, r2, r3, addr) \
    asm volatile("ldmatrix.sync.aligned.m8n8.x4.shared.b16 {%0,%1,%2,%3}, [%4];" \
        : "=r"(r0), "=r"(r1), "=r"(r2), "=r"(r3) : "r"(addr))

__device__ __forceinline__ void mma_16816(float* c, const uint32_t* a, const uint32_t* b) {
    asm volatile(
        "mma.sync.aligned.m16n8k16.row.col.f32.f16.f16.f32 "
        "{%0,%1,%2,%3}, {%4,%5,%6,%7}, {%8,%9}, {%0,%1,%2,%3};"
        : "+f"(c[0]), "+f"(c[1]), "+f"(c[2]), "+f"(c[3])
        : "r"(a[0]), "r"(a[1]), "r"(a[2]), "r"(a[3]), "r"(b[0]), "r"(b[1]));
}

__device__ __forceinline__ void split2h(float x, __half& h, __half& m) {
    h = __float2half_rn(x);
    m = __float2half_rn(x - __half2float(h));
}

// ===================== fp16 split GEMM via mma.sync =====================
// C[8192, Nout](+epilogue) = escale * sum_terms A_c[8192,K] @ B_c[1024,K]^T
// NTERMS=3: 2 components/operand, 2-stage double buffer (2 syncs/chunk).
// NTERMS=1: h-only, 3-stage ring with a SINGLE sync per chunk.
// block tile 128x128, BK=32, 8 warps (warp tile 64x32), 2 CTA/SM.
//  MODE 0: v = escale*acc + bias[n]; store stride D_BOT; also split2 -> oc0/oc1
//  MODE 1: v = escale*acc;           store stride Nout, guard n<Nout
//  MODE 2: v = escale*acc + aux[m*D_BOT+n]; store stride D_BOT
//  MODE 3: v = escale*acc;           store stride Nout, guard
template <int NTERMS, int MODE>
__global__ void __launch_bounds__(256, 2)
gemm_mma(const __half* __restrict__ A, size_t sA,
         const __half* __restrict__ B, size_t sB,
         float* __restrict__ C, int K, int Nout, float escale,
         const float* __restrict__ aux,
         __half* __restrict__ oc0, __half* __restrict__ oc1)
{
    extern __shared__ __align__(128) char smem[];
    const uint32_t sb = smem_u32(smem);
    const int tid = threadIdx.x;
    const int wid = tid >> 5;
    const int lane = tid & 31;
    const int bm = blockIdx.y * 128;
    const int bn = blockIdx.x * 128;

    constexpr int NCL = (NTERMS == 1) ? 1 : 2;   // components loaded per operand
    constexpr int STAGES = (NTERMS == 1) ? 3 : 2;
    constexpr int TILEB = 128 * 80;              // 10240 B (64B data + 16B pad per row)
    constexpr int STAGE = 2 * NCL * TILEB;

    const int wm = (wid >> 2) * 64;
    const int wn = (wid & 3) * 32;

    // A x4: 16 rows (lane&15), 16B half by lane>>4
    const uint32_t a_lo = (uint32_t)((lane & 15) * 80 + (lane >> 4) * 16);
    // B x4: row-octet pair — rows (lane&7) + ((lane>>4)&1)*8, 16B half by bit3
    const uint32_t b4_lo = (uint32_t)(((lane & 7) + ((lane >> 4) & 1) * 8) * 80
                                      + ((lane >> 3) & 1) * 16);

    const int l_row0 = tid >> 2;
    const int l_seg = tid & 3;

    float acc[4][4][4];
#pragma unroll
    for (int i = 0; i < 4; i++)
#pragma unroll
        for (int j = 0; j < 4; j++)
#pragma unroll
            for (int q = 0; q < 4; q++) acc[i][j][q] = 0.f;

    const int nch = K >> 5;

    auto load_chunk = [&](int ci) {
        const int s = ci % STAGES;
        const int k0 = ci << 5;
        const uint32_t st = sb + (uint32_t)s * STAGE;
#pragma unroll
        for (int c = 0; c < 2 * NCL; c++) {
            const __half* base = (c < NCL)
                ? A + (size_t)c * sA + (size_t)bm * K + k0
                : B + (size_t)(c - NCL) * sB + (size_t)bn * K + k0;
#pragma unroll
            for (int j = 0; j < 2; j++) {
                const int row = l_row0 + j * 64;
                cp16(st + (uint32_t)(c * TILEB + row * 80 + l_seg * 16),
                     base + (size_t)row * K + l_seg * 8);
            }
        }
        CP_COMMIT();
    };

    load_chunk(0);
    load_chunk(1);

    for (int i = 0; i < nch; i++) {
        CP_WAIT1();
        __syncthreads();
        if (STAGES == 3 && i + 2 < nch) load_chunk(i + 2);  // stage (i-1)%3, freed by sync
        const uint32_t st = sb + (uint32_t)(i % STAGES) * STAGE;
#pragma unroll
        for (int kk = 0; kk < 2; kk++) {
            // ---- hoist ALL fragments for this kk ----
            uint32_t bfr[NCL][4][2];
#pragma unroll
            for (int c = 0; c < NCL; c++)
#pragma unroll
                for (int np = 0; np < 2; np++)
                    LDSM_X4(bfr[c][np * 2][0], bfr[c][np * 2][1],
                            bfr[c][np * 2 + 1][0], bfr[c][np * 2 + 1][1],
                            st + (uint32_t)((NCL + c) * TILEB)
                               + (uint32_t)((wn + np * 16) * 80) + b4_lo
                               + (uint32_t)(kk * 32));
            uint32_t afr[NCL][4][4];
#pragma unroll
            for (int c = 0; c < NCL; c++)
#pragma unroll
                for (int mt = 0; mt < 4; mt++)
                    LDSM_X4(afr[c][mt][0], afr[c][mt][1], afr[c][mt][2], afr[c][mt][3],
                            st + (uint32_t)(c * TILEB) + (uint32_t)(wm * 80) + a_lo
                               + (uint32_t)(mt * 16 * 80 + kk * 32));
            // ---- uninterrupted MMA stream ----
#pragma unroll
            for (int ca = 0; ca < NCL; ca++)
#pragma unroll
                for (int cb = 0; cb < NCL; cb++) {
                    if (NTERMS == 1 || ca + cb < 2) {
#pragma unroll
                        for (int mt = 0; mt < 4; mt++)
#pragma unroll
                            for (int nt = 0; nt < 4; nt++)
                                mma_16816(acc[mt][nt], afr[ca][mt], bfr[cb][nt]);
                    }
                }
        }
        if (STAGES == 2) {
            __syncthreads();
            if (i + 2 < nch) load_chunk(i + 2);
        }
    }

    // ---------------- epilogue ----------------
    const int r0 = lane >> 2;
    const int c0 = (lane & 3) * 2;
#pragma unroll
    for (int mt = 0; mt < 4; mt++) {
#pragma unroll
        for (int half = 0; half < 2; half++) {
            const int m = bm + wm + mt * 16 + r0 + half * 8;
#pragma unroll
            for (int nt = 0; nt < 4; nt++) {
                const int n = bn + wn + nt * 8 + c0;
                float v0 = acc[mt][nt][half * 2 + 0] * escale;
                float v1 = acc[mt][nt][half * 2 + 1] * escale;
                if (MODE == 0) {
                    const float2 bs = *reinterpret_cast<const float2*>(aux + n);
                    v0 += bs.x; v1 += bs.y;
                    const size_t o = (size_t)m * D_BOT + n;
                    *reinterpret_cast<float2*>(C + o) = make_float2(v0, v1);
                    __half h0, mm0, h1, mm1;
                    split2h(v0, h0, mm0); split2h(v1, h1, mm1);
                    __half2 ph; ph.x = h0; ph.y = h1;
                    __half2 pm; pm.x = mm0; pm.y = mm1;
                    *reinterpret_cast<__half2*>(oc0 + o) = ph;
                    *reinterpret_cast<__half2*>(oc1 + o) = pm;
                } else if (MODE == 2) {
                    const float2 r = *reinterpret_cast<const float2*>(aux + (size_t)m * D_BOT + n);
                    v0 += r.x; v1 += r.y;
                    *reinterpret_cast<float2*>(C + (size_t)m * D_BOT + n) = make_float2(v0, v1);
                } else {
                    if (n < Nout)
                        *reinterpret_cast<float2*>(C + (size_t)m * Nout + n) = make_float2(v0, v1);
                }
            }
        }
    }
}

// ===================== fused prep: feature split + ALL weight prep =====================
// blocks [0, NB_FEAT)   : features split2 (no scale), 8192x2048
// blocks [.., +NB_WB)   : W_b split2 (*SW), 1024x2048
// blocks [.., +NB_W1)   : W1 split2 (*SW), pad to 1024x1024
// blocks [.., +NB_W2)   : W2 h-only convert, pad to 1024x1024
// blocks [.., +NB_CT)   : centroid transpose -> cTh [D_BOT, C_PAD]
#define NB_FEAT 1024
#define NB_WB 256
#define NB_W1 128
#define NB_W2 64
#define NB_CT (32 * 32)
__global__ void __launch_bounds__(256)
prep_all(const float* __restrict__ features,
         const float* __restrict__ W_b, const float* __restrict__ W1,
         const float* __restrict__ W2, const float* __restrict__ centroid,
         __half* __restrict__ f0, __half* __restrict__ f1,
         __half* __restrict__ wb0, __half* __restrict__ wb1,
         __half* __restrict__ w10, __half* __restrict__ w11,
         __half* __restrict__ w2h)
{
    const int b = blockIdx.x;
    if (b < NB_FEAT) {
        const size_t total4 = (size_t)B_ROWS * D_INF / 4;
        for (size_t i = (size_t)b * blockDim.x + threadIdx.x; i < total4;
             i += (size_t)NB_FEAT * blockDim.x) {
            float4 v = reinterpret_cast<const float4*>(features)[i];
            const float x[4] = {v.x, v.y, v.z, v.w};
            __half h[4], m[4];
#pragma unroll
            for (int p = 0; p < 4; p++) split2h(x[p], h[p], m[p]);
            __half2 ph0; ph0.x = h[0]; ph0.y = h[1];
            __half2 ph1; ph1.x = h[2]; ph1.y = h[3];
            __half2 pm0; pm0.x = m[0]; pm0.y = m[1];
            __half2 pm1; pm1.x = m[2]; pm1.y = m[3];
            uint2 pk0, pk1;
            pk0.x = *reinterpret_cast<uint32_t*>(&ph0);
            pk0.y = *reinterpret_cast<uint32_t*>(&ph1);
            pk1.x = *reinterpret_cast<uint32_t*>(&pm0);
            pk1.y = *reinterpret_cast<uint32_t*>(&pm1);
            reinterpret_cast<uint2*>(f0)[i] = pk0;
            reinterpret_cast<uint2*>(f1)[i] = pk1;
        }
    } else if (b < NB_FEAT + NB_WB) {
        const int bb = b - NB_FEAT;
        const size_t total4 = (size_t)D_BOT * D_INF / 4;
        for (size_t i = (size_t)bb * blockDim.x + threadIdx.x; i < total4;
             i += (size_t)NB_WB * blockDim.x) {
            float4 v = reinterpret_cast<const float4*>(W_b)[i];
            const float x[4] = {v.x * SW, v.y * SW, v.z * SW, v.w * SW};
            __half h[4], m[4];
#pragma unroll
            for (int p = 0; p < 4; p++) split2h(x[p], h[p], m[p]);
            __half2 ph0; ph0.x = h[0]; ph0.y = h[1];
            __half2 ph1; ph1.x = h[2]; ph1.y = h[3];
            __half2 pm0; pm0.x = m[0]; pm0.y = m[1];
            __half2 pm1; pm1.x = m[2]; pm1.y = m[3];
            uint2 pk0, pk1;
            pk0.x = *reinterpret_cast<uint32_t*>(&ph0);
            pk0.y = *reinterpret_cast<uint32_t*>(&ph1);
            pk1.x = *reinterpret_cast<uint32_t*>(&pm0);
            pk1.y = *reinterpret_cast<uint32_t*>(&pm1);
            reinterpret_cast<uint2*>(wb0)[i] = pk0;
            reinterpret_cast<uint2*>(wb1)[i] = pk1;
        }
    } else if (b < NB_FEAT + NB_WB + NB_W1) {
        const int bb = b - NB_FEAT - NB_WB;
        const size_t total4 = (size_t)C_PAD * D_BOT / 4;
        for (size_t i = (size_t)bb * blockDim.x + threadIdx.x; i < total4;
             i += (size_t)NB_W1 * blockDim.x) {
            const int row = (int)((i * 4) >> 10);
            float4 v = (row < C_CLS) ? reinterpret_cast<const float4*>(W1)[i]
                                     : make_float4(0.f, 0.f, 0.f, 0.f);
            const float x[4] = {v.x * SW, v.y * SW, v.z * SW, v.w * SW};
            __half h[4], m[4];
#pragma unroll
            for (int p = 0; p < 4; p++) split2h(x[p], h[p], m[p]);
            __half2 ph0; ph0.x = h[0]; ph0.y = h[1];
            __half2 ph1; ph1.x = h[2]; ph1.y = h[3];
            __half2 pm0; pm0.x = m[0]; pm0.y = m[1];
            __half2 pm1; pm1.x = m[2]; pm1.y = m[3];
            uint2 pk0, pk1;
            pk0.x = *reinterpret_cast<uint32_t*>(&ph0);
            pk0.y = *reinterpret_cast<uint32_t*>(&ph1);
            pk1.x = *reinterpret_cast<uint32_t*>(&pm0);
            pk1.y = *reinterpret_cast<uint32_t*>(&pm1);
            reinterpret_cast<uint2*>(w10)[i] = pk0;
            reinterpret_cast<uint2*>(w11)[i] = pk1;
        }
    } else if (b < NB_FEAT + NB_WB + NB_W1 + NB_W2) {
        const int bb = b - NB_FEAT - NB_WB - NB_W1;
        const size_t total4 = (size_t)C_PAD * D_BOT / 4;
        for (size_t i = (size_t)bb * blockDim.x + threadIdx.x; i < total4;
             i += (size_t)NB_W2 * blockDim.x) {
            const int row = (int)((i * 4) >> 10);
            float4 v = (row < C_CLS) ? reinterpret_cast<const float4*>(W2)[i]
                                     : make_float4(0.f, 0.f, 0.f, 0.f);
            __half2 p0; p0.x = __float2half_rn(v.x); p0.y = __float2half_rn(v.y);
            __half2 p1; p1.x = __float2half_rn(v.z); p1.y = __float2half_rn(v.w);
            uint2 pk;
            pk.x = *reinterpret_cast<uint32_t*>(&p0);
            pk.y = *reinterpret_cast<uint32_t*>(&p1);
            reinterpret_cast<uint2*>(w2h)[i] = pk;
        }
    } else {
        __shared__ float tile[32][33];
        const int t = b - NB_FEAT - NB_WB - NB_W1 - NB_W2;
        const int bx = (t & 31) * 32;
        const int by = (t >> 5) * 32;
        const int tx = threadIdx.x & 31;
        const int ty = threadIdx.x >> 5;
        const int x = bx + tx;
#pragma unroll
        for (int i = 0; i < 32; i += 8) {
            const int c = by + ty + i;
            tile[ty + i][tx] = (c < C_CLS) ? centroid[(size_t)c * D_BOT + x] : 0.f;
        }
        __syncthreads();
        const int c2 = by + tx;
#pragma unroll
        for (int i = 0; i < 32; i += 8) {
            const int d2 = bx + ty + i;
            g_cTh[(size_t)d2 * C_PAD + c2] = __float2half_rn(tile[tx][ty + i]);
        }
    }
}

// fused warp-per-row: L2 norm of features_aug row, h-only convert of x = row/||row||
__global__ void __launch_bounds__(256)
norm_h(const float* __restrict__ src, __half* __restrict__ c0)
{
    const int warp = threadIdx.x >> 5;
    const int lane = threadIdx.x & 31;
    const int row = blockIdx.x * 8 + warp;
    const float4* xr = reinterpret_cast<const float4*>(src + (size_t)row * D_BOT);

    float4 vv[8];
    float s = 0.f;
#pragma unroll
    for (int i = 0; i < 8; i++) {
        vv[i] = xr[lane + i * 32];
        s += vv[i].x * vv[i].x + vv[i].y * vv[i].y + vv[i].z * vv[i].z + vv[i].w * vv[i].w;
    }
#pragma unroll
    for (int off = 16; off > 0; off >>= 1)
        s += __shfl_xor_sync(0xFFFFFFFFu, s, off);
    const float inv = 1.f / fmaxf(sqrtf(s), EPSN);

    uint2* outp = reinterpret_cast<uint2*>(c0 + (size_t)row * D_BOT);
#pragma unroll
    for (int i = 0; i < 8; i++) {
        __half2 p0; p0.x = __float2half_rn(vv[i].x * inv); p0.y = __float2half_rn(vv[i].y * inv);
        __half2 p1; p1.x = __float2half_rn(vv[i].z * inv); p1.y = __float2half_rn(vv[i].w * inv);
        uint2 pk;
        pk.x = *reinterpret_cast<uint32_t*>(&p0);
        pk.y = *reinterpret_cast<uint32_t*>(&p1);
        outp[lane + i * 32] = pk;
    }
}

// ============ warp-per-row masked softmax -> sm1 h-only (col-padded, fp16) ==========
__global__ void __launch_bounds__(256)
mask_softmax(const float* __restrict__ logits)
{
    const int warp = threadIdx.x >> 5;
    const int lane = threadIdx.x & 31;
    const int row = blockIdx.x * 8 + warp;
    const float* x = logits + (size_t)row * C_CLS;

    float v[32];
    float lmax = -INFINITY;
    int limax = C_PAD;
#pragma unroll
    for (int i = 0; i < 16; i++) {
        const int j = i * 64 + lane * 2;
        const float a = (j < C_CLS) ? x[j] : -INFINITY;
        const float b = (j + 1 < C_CLS) ? x[j + 1] : -INFINITY;
        v[2 * i] = a; v[2 * i + 1] = b;
        if (a > lmax) { lmax = a; limax = j; }
        if (b > lmax) { lmax = b; limax = j + 1; }
    }
#pragma unroll
    for (int off = 16; off > 0; off >>= 1) {
        const float ov = __shfl_xor_sync(0xFFFFFFFFu, lmax, off);
        const int   oi = __shfl_xor_sync(0xFFFFFFFFu, limax, off);
        if (ov > lmax || (ov == lmax && oi < limax)) { lmax = ov; limax = oi; }
    }
    const int predict = limax;
    const float rowmax = lmax;
    const bool priv = (predict >= SHARE);

    float e[32];
    float lsum = 0.f;
#pragma unroll
    for (int i = 0; i < 32; i++) {
        const int j = (i >> 1) * 64 + lane * 2 + (i & 1);
        float ee = 0.f;
        if (j < C_CLS) {
            bool mask;
            if (j == predict) mask = false;
            else if (priv)    mask = true;
            else              mask = (j < SHARE);
            ee = expf((mask ? NEG_FILL : v[i]) - rowmax);
            lsum += ee;
        }
        e[i] = ee;
    }
#pragma unroll
    for (int off = 16; off > 0; off >>= 1)
        lsum += __shfl_xor_sync(0xFFFFFFFFu, lsum, off);
    const float inv = 1.f / lsum;

    __half* o0 = g_sm1h + (size_t)row * C_PAD;
#pragma unroll
    for (int i = 0; i < 16; i++) {
        const int j = i * 64 + lane * 2;
        __half2 p;
        p.x = __float2half_rn(e[2 * i] * inv);
        p.y = __float2half_rn(e[2 * i + 1] * inv);
        *reinterpret_cast<__half2*>(o0 + j) = p;
    }
}

// ===================== warp-per-row plain softmax =====================
__global__ void __launch_bounds__(256)
softmax_rows(const float* __restrict__ in, float* __restrict__ outp)
{
    const int warp = threadIdx.x >> 5;
    const int lane = threadIdx.x & 31;
    const int row = blockIdx.x * 8 + warp;
    const float* x = in + (size_t)row * C_CLS;

    float v[32];
    float lmax = -INFINITY;
#pragma unroll
    for (int i = 0; i < 16; i++) {
        const int j = i * 64 + lane * 2;
        v[2 * i]     = (j < C_CLS) ? x[j] : -INFINITY;
        v[2 * i + 1] = (j + 1 < C_CLS) ? x[j + 1] : -INFINITY;
        lmax = fmaxf(lmax, fmaxf(v[2 * i], v[2 * i + 1]));
    }
#pragma unroll
    for (int off = 16; off > 0; off >>= 1)
        lmax = fmaxf(lmax, __shfl_xor_sync(0xFFFFFFFFu, lmax, off));

    float e[32];
    float lsum = 0.f;
#pragma unroll
    for (int i = 0; i < 32; i++) {
        const int j = (i >> 1) * 64 + lane * 2 + (i & 1);
        float ee = 0.f;
        if (j < C_CLS) { ee = expf(v[i] - lmax); lsum += ee; }
        e[i] = ee;
    }
#pragma unroll
    for (int off = 16; off > 0; off >>= 1)
        lsum += __shfl_xor_sync(0xFFFFFFFFu, lsum, off);
    const float inv = 1.f / lsum;

    float* o = outp + (size_t)row * C_CLS;
#pragma unroll
    for (int i = 0; i < 16; i++) {
        const int j = i * 64 + lane * 2;
        if (j + 1 < C_CLS) {
            *reinterpret_cast<float2*>(o + j) = make_float2(e[2 * i] * inv, e[2 * i + 1] * inv);
        } else if (j < C_CLS) {
            o[j] = e[2 * i] * inv;
        }
    }
}

// =====================================================================
extern "C" void kernel_launch(void* const* d_in, const int* in_sizes, int n_in,
                              void* d_out, int out_size)
{
    const float* features = (const float*)d_in[0];
    const float* W_b      = (const float*)d_in[1];
    const float* b_b      = (const float*)d_in[2];
    const float* W1       = (const float*)d_in[3];
    const float* W2       = (const float*)d_in[4];
    const float* centroid = (const float*)d_in[5];

    float* out = (float*)d_out;
    float* feats        = out;
    float* features_aug = feats + (size_t)B_ROWS * D_BOT;
    float* outputs1     = features_aug + (size_t)B_ROWS * D_BOT;
    float* outputs2     = outputs1 + (size_t)B_ROWS * C_CLS;
    float* softmax_out  = outputs2 + (size_t)B_ROWS * C_CLS;

    __half *feat2, *Wb2, *feats2, *W1s, *sm1h, *cTh, *faugh, *W2h;
    cudaGetSymbolAddress((void**)&feat2,  g_feat2);
    cudaGetSymbolAddress((void**)&Wb2,    g_Wb2);
    cudaGetSymbolAddress((void**)&feats2, g_feats2);
    cudaGetSymbolAddress((void**)&W1s,    g_W1s);
    cudaGetSymbolAddress((void**)&sm1h,   g_sm1h);
    cudaGetSymbolAddress((void**)&cTh,    g_cTh);
    cudaGetSymbolAddress((void**)&faugh,  g_faugh);
    cudaGetSymbolAddress((void**)&W2h,    g_W2h);

    const size_t S_feat  = (size_t)B_ROWS * D_INF;
    const size_t S_Wb    = (size_t)D_BOT  * D_INF;
    const size_t S_feats = (size_t)B_ROWS * D_BOT;
    const size_t S_W1    = (size_t)C_PAD  * D_BOT;

    constexpr int TILEB = 128 * 80;
    constexpr int SMEMG  = 2 * 4 * TILEB;   // 81920 — NTERMS=3, 2-stage, 2 CTAs/SM
    constexpr int SMEMG1 = 3 * 2 * TILEB;   // 61440 — NTERMS=1, 3-stage, 2 CTAs/SM
    cudaFuncSetAttribute(gemm_mma<3, 0>, cudaFuncAttributeMaxDynamicSharedMemorySize, SMEMG);
    cudaFuncSetAttribute(gemm_mma<3, 1>, cudaFuncAttributeMaxDynamicSharedMemorySize, SMEMG);
    cudaFuncSetAttribute(gemm_mma<1, 2>, cudaFuncAttributeMaxDynamicSharedMemorySize, SMEMG1);
    cudaFuncSetAttribute(gemm_mma<1, 3>, cudaFuncAttributeMaxDynamicSharedMemorySize, SMEMG1);

    const dim3 blk(256);
    const dim3 grid8(8, 64);
    const float invSW = 1.0f / SW;

    // ALL input prep (feature split + weight prep) in ONE launch
    prep_all<<<NB_FEAT + NB_WB + NB_W1 + NB_W2 + NB_CT, blk>>>(
        features, W_b, W1, W2, centroid,
        feat2, feat2 + S_feat, Wb2, Wb2 + S_Wb, W1s, W1s + S_W1, W2h);

    // GEMM1: feats = features @ W_b^T + b_b (3-term fp16 split; epilogue emits feats2)
    gemm_mma<3, 0><<<grid8, blk, SMEMG>>>(feat2, S_feat, Wb2, S_Wb, feats, D_INF, D_BOT,
                                          invSW, b_b, feats2, feats2 + S_feats);

    // GEMM2: outputs1 = feats @ W1^T (3-term — argmax-critical, do not cut)
    gemm_mma<3, 1><<<grid8, blk, SMEMG>>>(feats2, S_feats, W1s, S_W1, outputs1, D_BOT, C_CLS,
                                          invSW, nullptr, nullptr, nullptr);

    // masked softmax (warp-per-row, h-only sm1)
    mask_softmax<<<B_ROWS / 8, blk>>>(outputs1);

    // GEMM3: features_aug = sm1 @ centroid + feats (1-term h*h, 3-stage single-sync)
    gemm_mma<1, 2><<<grid8, blk, SMEMG1>>>(sm1h, 0, cTh, 0, features_aug, C_PAD, D_BOT,
                                           1.0f, feats, nullptr, nullptr);

    // fused warp-per-row normalize + h-only convert
    norm_h<<<B_ROWS / 8, blk>>>(features_aug, faugh);

    // GEMM4: outputs2 = x @ W2^T / TEMP (1-term h*h, 3-stage single-sync)
    gemm_mma<1, 3><<<grid8, blk, SMEMG1>>>(faugh, 0, W2h, 0, outputs2, D_BOT, C_CLS,
                                           20.0f, nullptr, nullptr, nullptr);

    softmax_rows<<<B_ROWS / 8, blk>>>(outputs2, softmax_out);
}